// round 13
// baseline (speedup 1.0000x reference)
#include <cuda_runtime.h>
#include <cuda_fp16.h>
#include <cstdint>

constexpr int S_LEN = 2048, HID = 2048, NH = 16, QR = 1536, KVR = 512;
constexpr int DN = 128, DR = 64, DQK = 192, DV = 128;
constexpr float EPS = 1e-6f;

__device__ float g_qa [S_LEN * QR];
__device__ float g_q  [S_LEN * NH * DQK];
__device__ float g_kva[S_LEN * (KVR + DR)];
__device__ float g_kvb[S_LEN * NH * (DN + DV)];

__device__ unsigned g_Qh[NH * (S_LEN/16) * 12 * 128];
__device__ unsigned g_Ql[NH * (S_LEN/16) * 12 * 128];
__device__ unsigned g_Kh[NH * (S_LEN/8)  * 12 * 64];
__device__ unsigned g_Kl[NH * (S_LEN/8)  * 12 * 64];
__device__ unsigned g_Vh[NH * (S_LEN/16) * 16 * 64];
__device__ unsigned g_Vl[NH * (S_LEN/16) * 16 * 64];

__device__ unsigned g_AhsH [2097152], g_AhsL [2097152];
__device__ unsigned g_AqaH [1572864], g_AqaL [1572864];
__device__ unsigned g_AkvH [524288],  g_AkvL [524288];
__device__ unsigned g_AatH [2097152], g_AatL [2097152];
__device__ unsigned g_BqaH [1572864], g_BqaL [1572864];
__device__ unsigned g_BqbH [2359296], g_BqbL [2359296];
__device__ unsigned g_BkaH [655360],  g_BkaL [655360];
__device__ unsigned g_BkbH [1048576], g_BkbL [1048576];
__device__ unsigned g_BowH [2097152], g_BowL [2097152];

__device__ __forceinline__ void split2(float x0, float x1,
                                       unsigned& hi, unsigned& lo) {
    __half h0 = __float2half_rn(x0), h1 = __float2half_rn(x1);
    __half l0 = __float2half_rn(x0 - __half2float(h0));
    __half l1 = __float2half_rn(x1 - __half2float(h1));
    hi = (unsigned)__half_as_ushort(h0) | ((unsigned)__half_as_ushort(h1) << 16);
    lo = (unsigned)__half_as_ushort(l0) | ((unsigned)__half_as_ushort(l1) << 16);
}

__device__ __forceinline__ void mma16(float* c, const uint4& a, const uint2& b) {
    asm volatile(
        "mma.sync.aligned.m16n8k16.row.col.f32.f16.f16.f32 "
        "{%0,%1,%2,%3}, {%4,%5,%6,%7}, {%8,%9}, {%0,%1,%2,%3};"
        : "+f"(c[0]), "+f"(c[1]), "+f"(c[2]), "+f"(c[3])
        : "r"(a.x), "r"(a.y), "r"(a.z), "r"(a.w), "r"(b.x), "r"(b.y));
}

__device__ __forceinline__ void cpa16(uint32_t dst, const void* src) {
    asm volatile("cp.async.cg.shared.global [%0], [%1], 16;"
                 :: "r"(dst), "l"(src) : "memory");
}

// ---------------------------------------------------------------------------
__global__ void __launch_bounds__(256) convA_kernel(
    const float* __restrict__ X, unsigned* __restrict__ Ph,
    unsigned* __restrict__ Pl, int K)
{
    size_t id = (size_t)blockIdx.x * 256 + threadIdx.x;
    int m = (int)(id / (K >> 1));
    int d = (int)(id % (K >> 1)) * 2;
    float2 v = *(const float2*)&X[(size_t)m * K + d];
    unsigned hi, lo; split2(v.x, v.y, hi, lo);
    size_t off = ((size_t)(m >> 4) * (K >> 4) + (d >> 4)) * 128
               + ((m & 7) * 4 + ((d & 7) >> 1)) * 4
               + ((d >> 3) & 1) * 2 + ((m >> 3) & 1);
    Ph[off] = hi; Pl[off] = lo;
}

__global__ void __launch_bounds__(256) convB_kernel(
    const float* __restrict__ W, unsigned* __restrict__ Ph,
    unsigned* __restrict__ Pl, int N, int K)
{
    size_t id = (size_t)blockIdx.x * 256 + threadIdx.x;
    int n = (int)(id / (K >> 1));
    int d = (int)(id % (K >> 1)) * 2;
    float v0 = 0.f, v1 = 0.f;
    if (n < N) { float2 v = *(const float2*)&W[(size_t)n * K + d]; v0 = v.x; v1 = v.y; }
    unsigned hi, lo; split2(v0, v1, hi, lo);
    size_t off = ((size_t)(n >> 3) * (K >> 4) + (d >> 4)) * 64
               + ((n & 7) * 4 + ((d & 7) >> 1)) * 2 + ((d >> 3) & 1);
    Ph[off] = hi; Pl[off] = lo;
}

// ---------------------------------------------------------------------------
__global__ void __launch_bounds__(256, 2) gemm_fr_kernel(
    const unsigned* __restrict__ Ah, const unsigned* __restrict__ Al,
    const unsigned* __restrict__ Bh, const unsigned* __restrict__ Bl,
    float* __restrict__ C, int N, int K)
{
    __shared__ unsigned sm[2][4][2048];

    const int tid = threadIdx.x, lane = tid & 31, warp = tid >> 5;
    const int wm = warp >> 2, wn = warp & 3;
    const int m0t = blockIdx.y * 8, n0t = blockIdx.x * 16;
    const int KT = K >> 4;

    const int f0 = tid, f1 = tid + 256;
    const int aM0 = f0 >> 6, aK0 = (f0 & 63) >> 5, aW0 = f0 & 31;
    const int aM1 = f1 >> 6, aK1 = (f1 & 63) >> 5, aW1 = f1 & 31;
    const size_t aS0 = ((size_t)(m0t + aM0) * KT + aK0) * 128 + aW0 * 4;
    const size_t aS1 = ((size_t)(m0t + aM1) * KT + aK1) * 128 + aW1 * 4;
    const int aD0 = (aM0 * 2 + aK0) * 128 + aW0 * 4;
    const int aD1 = (aM1 * 2 + aK1) * 128 + aW1 * 4;
    const int bN0 = f0 >> 5, bK0 = (f0 & 31) >> 4, bW0 = f0 & 15;
    const int bN1 = f1 >> 5, bK1 = (f1 & 31) >> 4, bW1 = f1 & 15;
    const size_t bS0 = ((size_t)(n0t + bN0) * KT + bK0) * 64 + bW0 * 4;
    const size_t bS1 = ((size_t)(n0t + bN1) * KT + bK1) * 64 + bW1 * 4;
    const int bD0 = (bN0 * 2 + bK0) * 64 + bW0 * 4;
    const int bD1 = (bN1 * 2 + bK1) * 64 + bW1 * 4;

    const uint32_t sb = (uint32_t)__cvta_generic_to_shared(&sm[0][0][0]);
    auto issue = [&](int c, int st) {
        const size_t ao = (size_t)c * 256, bo = (size_t)c * 128;
        const uint32_t s0 = sb + (uint32_t)(st * 4) * 8192;
        cpa16(s0 + aD0 * 4,          Ah + aS0 + ao);
        cpa16(s0 + aD1 * 4,          Ah + aS1 + ao);
        cpa16(s0 + 8192  + aD0 * 4,  Al + aS0 + ao);
        cpa16(s0 + 8192  + aD1 * 4,  Al + aS1 + ao);
        cpa16(s0 + 16384 + bD0 * 4,  Bh + bS0 + bo);
        cpa16(s0 + 16384 + bD1 * 4,  Bh + bS1 + bo);
        cpa16(s0 + 24576 + bD0 * 4,  Bl + bS0 + bo);
        cpa16(s0 + 24576 + bD1 * 4,  Bl + bS1 + bo);
        asm volatile("cp.async.commit_group;" ::: "memory");
    };

    float acc[4][4][4];
    #pragma unroll
    for (int i = 0; i < 4; i++)
        #pragma unroll
        for (int j = 0; j < 4; j++)
            #pragma unroll
            for (int r = 0; r < 4; r++) acc[i][j][r] = 0.f;

    const int nc = K >> 5;
    issue(0, 0);

    for (int c = 0; c < nc; c++) {
        const int s = c & 1;
        if (c + 1 < nc) {
            issue(c + 1, s ^ 1);
            asm volatile("cp.async.wait_group 1;" ::: "memory");
        } else {
            asm volatile("cp.async.wait_group 0;" ::: "memory");
        }
        __syncthreads();

        #pragma unroll
        for (int kt = 0; kt < 2; kt++) {
            uint4 a_h[4], a_l[4];
            #pragma unroll
            for (int i = 0; i < 4; i++) {
                int off = ((wm * 4 + i) * 2 + kt) * 128 + lane * 4;
                a_h[i] = *(const uint4*)&sm[s][0][off];
                a_l[i] = *(const uint4*)&sm[s][1][off];
            }
            #pragma unroll
            for (int jp = 0; jp < 2; jp++) {
                uint2 b_h[2], b_l[2];
                #pragma unroll
                for (int jj = 0; jj < 2; jj++) {
                    int off = ((wn * 4 + jp * 2 + jj) * 2 + kt) * 64 + lane * 2;
                    b_h[jj] = *(const uint2*)&sm[s][2][off];
                    b_l[jj] = *(const uint2*)&sm[s][3][off];
                }
                #pragma unroll
                for (int jj = 0; jj < 2; jj++)
                    #pragma unroll
                    for (int i = 0; i < 4; i++)
                        mma16(acc[i][jp*2+jj], a_h[i], b_h[jj]);
                #pragma unroll
                for (int jj = 0; jj < 2; jj++)
                    #pragma unroll
                    for (int i = 0; i < 4; i++)
                        mma16(acc[i][jp*2+jj], a_h[i], b_l[jj]);
                #pragma unroll
                for (int jj = 0; jj < 2; jj++)
                    #pragma unroll
                    for (int i = 0; i < 4; i++)
                        mma16(acc[i][jp*2+jj], a_l[i], b_h[jj]);
            }
        }
        __syncthreads();
    }

    const int g = lane >> 2, q = lane & 3;
    const int m0 = blockIdx.y * 128, n0 = blockIdx.x * 128;
    #pragma unroll
    for (int i = 0; i < 4; i++) {
        const int row = m0 + wm * 64 + i * 16 + g;
        #pragma unroll
        for (int j = 0; j < 4; j++) {
            const int colb = n0 + wn * 32 + j * 8;
            if (colb < N) {
                const int col = colb + 2 * q;
                *(float2*)&C[(size_t)row * N + col] =
                    make_float2(acc[i][j][0], acc[i][j][1]);
                *(float2*)&C[(size_t)(row + 8) * N + col] =
                    make_float2(acc[i][j][2], acc[i][j][3]);
            }
        }
    }
}

// ---------------------------------------------------------------------------
__global__ void __launch_bounds__(256) rmsnormA_kernel(
    const float* __restrict__ x, const float* __restrict__ w,
    unsigned* __restrict__ Ph, unsigned* __restrict__ Pl, int ld, int n)
{
    const int row = blockIdx.x;
    const float* xr = x + (size_t)row * ld;
    float s = 0.f;
    for (int i = threadIdx.x; i < n; i += 256) { float v = xr[i]; s += v * v; }
    __shared__ float red[8];
    #pragma unroll
    for (int o = 16; o; o >>= 1) s += __shfl_xor_sync(0xffffffffu, s, o);
    if ((threadIdx.x & 31) == 0) red[threadIdx.x >> 5] = s;
    __syncthreads();
    if (threadIdx.x < 32) {
        float v = (threadIdx.x < 8) ? red[threadIdx.x] : 0.f;
        #pragma unroll
        for (int o = 4; o; o >>= 1) v += __shfl_xor_sync(0xffffffffu, v, o);
        if (threadIdx.x == 0) red[0] = v;
    }
    __syncthreads();
    const float r = rsqrtf(red[0] / (float)n + EPS);
    for (int dp = threadIdx.x; dp < (n >> 1); dp += 256) {
        int d = dp * 2;
        float v0 = w[d] * xr[d] * r, v1 = w[d + 1] * xr[d + 1] * r;
        unsigned hi, lo; split2(v0, v1, hi, lo);
        size_t off = ((size_t)(row >> 4) * (n >> 4) + (d >> 4)) * 128
                   + ((row & 7) * 4 + ((d & 7) >> 1)) * 4
                   + ((d >> 3) & 1) * 2 + ((row >> 3) & 1);
        Ph[off] = hi; Pl[off] = lo;
    }
}

// ---------------------------------------------------------------------------
__global__ void __launch_bounds__(256) assemble_kernel(
    const void* __restrict__ pos_ids)
{
    const int b = blockIdx.x, t0 = 2 * b, tid = threadIdx.x;
    const int h = blockIdx.y;
    __shared__ float cs[2][DR], sn[2][DR], kr[2][DR];
    __shared__ float posv[2];

    if (tid < 2) {
        const int* p32 = (const int*)pos_ids;
        int t = t0 + tid;
        long long pv = (p32[1] == 0) ? ((const long long*)pos_ids)[t]
                                     : (long long)p32[t];
        posv[tid] = (float)pv;
    }
    __syncthreads();
    if (tid < 128) {
        int tok = tid >> 6, i = tid & 63, j = i & 31;
        double e = -((double)(2 * j) / 64.0) * 13.287712379549449;
        float ang = posv[tok] * (float)exp2(e);
        cs[tok][i] = cosf(ang); sn[tok][i] = sinf(ang);
    }
    __syncthreads();
    if (tid < 128) {
        int tok = tid >> 6, i = tid & 63;
        const float* kx = g_kva + (size_t)(t0 + tok) * (KVR + DR) + KVR;
        kr[tok][i] = (i < 32) ? kx[i] * cs[tok][i] - kx[i + 32] * sn[tok][i]
                              : kx[i] * cs[tok][i] + kx[i - 32] * sn[tok][i];
    }
    __syncthreads();

    const float scale = rsqrtf((float)DQK);

    if (tid < 192) {                                  // Q
        int tok = tid / 96, pp = tid % 96, d = 2 * pp;
        int t = t0 + tok;
        const float* qrow = g_q + (size_t)t * (NH * DQK) + h * DQK;
        float v0, v1;
        if (d < DN) { v0 = qrow[d]; v1 = qrow[d + 1]; }
        else {
            int i = d - DN;
            if (i < 32) {
                v0 = qrow[d]   * cs[tok][i]   - qrow[d + 32] * sn[tok][i];
                v1 = qrow[d+1] * cs[tok][i+1] - qrow[d + 33] * sn[tok][i+1];
            } else {
                v0 = qrow[d]   * cs[tok][i]   + qrow[d - 32] * sn[tok][i];
                v1 = qrow[d+1] * cs[tok][i+1] + qrow[d - 31] * sn[tok][i+1];
            }
        }
        v0 *= scale; v1 *= scale;
        unsigned hi, lo; split2(v0, v1, hi, lo);
        int mt = t >> 4, r = t & 15;
        size_t off = ((size_t)(h * 128 + mt) * 12 + (d >> 4)) * 128
                   + ((r & 7) * 4 + ((d & 7) >> 1)) * 4
                   + (((d >> 3) & 1) * 2 + (r >> 3));
        g_Qh[off] = hi; g_Ql[off] = lo;
    }
    if (tid < 192) {                                  // K
        int tok = tid / 96, pp = tid % 96, d = 2 * pp;
        int t = t0 + tok;
        const float* kvrow = g_kvb + (size_t)t * (NH*(DN+DV)) + h * (DN+DV);
        float v0, v1;
        if (d < DN) { v0 = kvrow[d]; v1 = kvrow[d + 1]; }
        else        { v0 = kr[tok][d - DN]; v1 = kr[tok][d - DN + 1]; }
        unsigned hi, lo; split2(v0, v1, hi, lo);
        int nt = t >> 3, n = t & 7;
        size_t off = ((size_t)(h * 256 + nt) * 12 + (d >> 4)) * 64
                   + (n * 4 + ((d & 7) >> 1)) * 2 + ((d >> 3) & 1);
        g_Kh[off] = hi; g_Kl[off] = lo;
    }
    if (tid >= 64 && tid < 192) {                     // V
        int d = tid - 64;
        float v0 = g_kvb[(size_t)t0     * (NH*(DN+DV)) + h*(DN+DV) + DN + d];
        float v1 = g_kvb[(size_t)(t0+1) * (NH*(DN+DV)) + h*(DN+DV) + DN + d];
        unsigned hi, lo; split2(v0, v1, hi, lo);
        size_t off = ((size_t)(h * 128 + (t0 >> 4)) * 16 + (d >> 3)) * 64
                   + ((d & 7) * 4 + ((t0 & 7) >> 1)) * 2 + ((t0 >> 3) & 1);
        g_Vh[off] = hi; g_Vl[off] = lo;
    }
}

// ---------------------------------------------------------------------------
// Flash attention: paired q-tiles for perfect load balance.
// Grid = 128 CTAs: pair p handles (qt = 15-p) then (qt = p) for head h.
// Per-pair iteration total = 2(16-p) + 2(p+1) = 34, uniform across CTAs.
// ---------------------------------------------------------------------------
constexpr int FL_STAGE = 20480;
constexpr size_t FLASH_SMEM_BYTES = (12288 + 2 * FL_STAGE) * 4;

__device__ __forceinline__ void flash_tile(
    int qt, int h, unsigned* smu, uint32_t sb,
    int tid, int wid, int lane, int g, int q)
{
    unsigned* QL = smu;
    const int q0 = qt * 128;

    uint4 qh[12];
    {
        const size_t qbase = (size_t)(h * 128 + qt * 8 + wid) * 12 * 128;
        #pragma unroll
        for (int kt = 0; kt < 12; kt++)
            qh[kt] = *(const uint4*)&g_Qh[qbase + kt * 128 + lane * 4];
        const uint4* gl = (const uint4*)(g_Ql + (size_t)(h * 128 + qt * 8) * 1536);
        uint4* dl = (uint4*)QL;
        #pragma unroll
        for (int j = 0; j < 12; j++) dl[j * 256 + tid] = gl[j * 256 + tid];
    }

    const int niter = 2 * (qt + 1);
    const int wrow0 = q0 + wid * 16;

    auto issue = [&](int it, int st) {
        const uint4* gkh = (const uint4*)(g_Kh + (size_t)(h * 256 + it * 8) * 768);
        const uint4* gkl = (const uint4*)(g_Kl + (size_t)(h * 256 + it * 8) * 768);
        const uint4* gvh = (const uint4*)(g_Vh + (size_t)(h * 128 + it * 4) * 1024);
        const uint4* gvl = (const uint4*)(g_Vl + (size_t)(h * 128 + it * 4) * 1024);
        const uint32_t s0 = sb + (12288u + (uint32_t)st * FL_STAGE) * 4;
        #pragma unroll
        for (int j = 0; j < 6; j++) {
            cpa16(s0 +         (j * 256 + tid) * 16, gkh + j * 256 + tid);
            cpa16(s0 + 24576 + (j * 256 + tid) * 16, gkl + j * 256 + tid);
        }
        #pragma unroll
        for (int j = 0; j < 4; j++) {
            cpa16(s0 + 49152 + (j * 256 + tid) * 16, gvh + j * 256 + tid);
            cpa16(s0 + 65536 + (j * 256 + tid) * 16, gvl + j * 256 + tid);
        }
        asm volatile("cp.async.commit_group;" ::: "memory");
    };

    float O[16][4];
    #pragma unroll
    for (int nt = 0; nt < 16; nt++)
        #pragma unroll
        for (int r = 0; r < 4; r++) O[nt][r] = 0.f;
    float m0 = -1e30f, m1 = -1e30f, l0 = 0.f, l1 = 0.f;

    issue(0, 0);

    for (int it = 0; it < niter; it++) {
        const int s = it & 1;
        const int k0 = it * 64;
        if (it + 1 < niter) {
            issue(it + 1, s ^ 1);
            asm volatile("cp.async.wait_group 1;" ::: "memory");
        } else {
            asm volatile("cp.async.wait_group 0;" ::: "memory");
        }
        __syncthreads();

        unsigned* KHs = smu + 12288 + s * FL_STAGE;
        unsigned* KLs = KHs + 6144;
        unsigned* VHs = KHs + 12288;
        unsigned* VLs = KHs + 16384;

        if (k0 <= wrow0 + 15) {
            float S[8][4];
            #pragma unroll
            for (int nt = 0; nt < 8; nt++)
                #pragma unroll
                for (int r = 0; r < 4; r++) S[nt][r] = 0.f;

            #pragma unroll
            for (int kt = 0; kt < 12; kt++) {
                uint4 qhv = qh[kt];
                uint4 qlv = *(const uint4*)&QL[wid * 1536 + kt * 128 + lane * 4];
                #pragma unroll
                for (int nt = 0; nt < 8; nt++) {
                    uint2 kh = *(const uint2*)&KHs[(nt * 12 + kt) * 64 + lane * 2];
                    uint2 kl = *(const uint2*)&KLs[(nt * 12 + kt) * 64 + lane * 2];
                    mma16(S[nt], qhv, kh);
                    mma16(S[nt], qhv, kl);
                    mma16(S[nt], qlv, kh);
                }
            }

            if (k0 + 63 > wrow0) {
                const int row0 = wrow0 + g, row1 = row0 + 8;
                #pragma unroll
                for (int nt = 0; nt < 8; nt++) {
                    int col = k0 + nt * 8 + 2 * q;
                    if (col     > row0) S[nt][0] = -1e30f;
                    if (col + 1 > row0) S[nt][1] = -1e30f;
                    if (col     > row1) S[nt][2] = -1e30f;
                    if (col + 1 > row1) S[nt][3] = -1e30f;
                }
            }

            float rm0 = -1e30f, rm1 = -1e30f;
            #pragma unroll
            for (int nt = 0; nt < 8; nt++) {
                rm0 = fmaxf(rm0, fmaxf(S[nt][0], S[nt][1]));
                rm1 = fmaxf(rm1, fmaxf(S[nt][2], S[nt][3]));
            }
            rm0 = fmaxf(rm0, __shfl_xor_sync(0xffffffffu, rm0, 1));
            rm0 = fmaxf(rm0, __shfl_xor_sync(0xffffffffu, rm0, 2));
            rm1 = fmaxf(rm1, __shfl_xor_sync(0xffffffffu, rm1, 1));
            rm1 = fmaxf(rm1, __shfl_xor_sync(0xffffffffu, rm1, 2));

            float mn0 = fmaxf(m0, rm0), mn1 = fmaxf(m1, rm1);
            float a0 = __expf(m0 - mn0), a1 = __expf(m1 - mn1);

            unsigned PH[8], PL[8], P8H[8], P8L[8];
            float s0 = 0.f, s1 = 0.f;
            #pragma unroll
            for (int nt = 0; nt < 8; nt++) {
                float p00 = __expf(S[nt][0] - mn0);
                float p01 = __expf(S[nt][1] - mn0);
                float p10 = __expf(S[nt][2] - mn1);
                float p11 = __expf(S[nt][3] - mn1);
                s0 += p00 + p01; s1 += p10 + p11;
                split2(p00, p01, PH[nt], PL[nt]);
                split2(p10, p11, P8H[nt], P8L[nt]);
            }
            s0 += __shfl_xor_sync(0xffffffffu, s0, 1);
            s0 += __shfl_xor_sync(0xffffffffu, s0, 2);
            s1 += __shfl_xor_sync(0xffffffffu, s1, 1);
            s1 += __shfl_xor_sync(0xffffffffu, s1, 2);

            l0 = l0 * a0 + s0; l1 = l1 * a1 + s1;
            m0 = mn0; m1 = mn1;

            #pragma unroll
            for (int nt = 0; nt < 16; nt++) {
                O[nt][0] *= a0; O[nt][1] *= a0;
                O[nt][2] *= a1; O[nt][3] *= a1;
            }

            #pragma unroll
            for (int kt2 = 0; kt2 < 4; kt2++) {
                uint4 ah = make_uint4(PH[2*kt2], P8H[2*kt2], PH[2*kt2+1], P8H[2*kt2+1]);
                uint4 al = make_uint4(PL[2*kt2], P8L[2*kt2], PL[2*kt2+1], P8L[2*kt2+1]);
                #pragma unroll
                for (int nt = 0; nt < 16; nt++) {
                    uint2 vh = *(const uint2*)&VHs[(kt2 * 16 + nt) * 64 + lane * 2];
                    uint2 vl = *(const uint2*)&VLs[(kt2 * 16 + nt) * 64 + lane * 2];
                    mma16(O[nt], ah, vh);
                    mma16(O[nt], ah, vl);
                    mma16(O[nt], al, vh);
                }
            }
        }
        __syncthreads();
    }

    const float inv0 = __fdividef(1.f, l0), inv1 = __fdividef(1.f, l1);
    const int row0 = wrow0 + g;
    const size_t baseRow = (size_t)(row0 >> 4) * 128;
    #pragma unroll
    for (int nt = 0; nt < 16; nt++) {
        const int ktv = h * 8 + (nt >> 1);
        const size_t off = (baseRow + ktv) * 128 + lane * 4 + (nt & 1) * 2;
        unsigned hi, lo;
        split2(O[nt][0] * inv0, O[nt][1] * inv0, hi, lo);
        g_AatH[off] = hi; g_AatL[off] = lo;
        split2(O[nt][2] * inv1, O[nt][3] * inv1, hi, lo);
        g_AatH[off + 1] = hi; g_AatL[off + 1] = lo;
    }
}

__global__ void __launch_bounds__(256) flash_kernel()
{
    const int bx = blockIdx.x;          // 0..127
    const int p  = bx >> 4;             // pair index 0..7
    const int h  = bx & 15;
    const int tid = threadIdx.x, wid = tid >> 5, lane = tid & 31;
    const int g = lane >> 2, q = lane & 3;

    extern __shared__ unsigned smu[];
    const uint32_t sb = (uint32_t)__cvta_generic_to_shared(smu);

    flash_tile(15 - p, h, smu, sb, tid, wid, lane, g, q);   // heavy tile
    flash_tile(p,      h, smu, sb, tid, wid, lane, g, q);   // light tile
}

// ---------------------------------------------------------------------------
extern "C" void kernel_launch(void* const* d_in, const int* in_sizes, int n_in,
                              void* d_out, int out_size)
{
    const float* hs       = (const float*)d_in[0];
    const void*  pos_ids  = d_in[1];
    const float* q_a_w    = (const float*)d_in[2];
    const float* q_a_ln_w = (const float*)d_in[3];
    const float* q_b_w    = (const float*)d_in[4];
    const float* kv_a_w   = (const float*)d_in[5];
    const float* kv_a_ln_w= (const float*)d_in[6];
    const float* kv_b_w   = (const float*)d_in[7];
    const float* o_w      = (const float*)d_in[8];
    float*       out      = (float*)d_out;

    float *p_qa, *p_q, *p_kva, *p_kvb;
    cudaGetSymbolAddress((void**)&p_qa,  g_qa);
    cudaGetSymbolAddress((void**)&p_q,   g_q);
    cudaGetSymbolAddress((void**)&p_kva, g_kva);
    cudaGetSymbolAddress((void**)&p_kvb, g_kvb);
    unsigned *AhsH,*AhsL,*AqaH,*AqaL,*AkvH,*AkvL,*AatH,*AatL;
    unsigned *BqaH,*BqaL,*BqbH,*BqbL,*BkaH,*BkaL,*BkbH,*BkbL,*BowH,*BowL;
    cudaGetSymbolAddress((void**)&AhsH, g_AhsH); cudaGetSymbolAddress((void**)&AhsL, g_AhsL);
    cudaGetSymbolAddress((void**)&AqaH, g_AqaH); cudaGetSymbolAddress((void**)&AqaL, g_AqaL);
    cudaGetSymbolAddress((void**)&AkvH, g_AkvH); cudaGetSymbolAddress((void**)&AkvL, g_AkvL);
    cudaGetSymbolAddress((void**)&AatH, g_AatH); cudaGetSymbolAddress((void**)&AatL, g_AatL);
    cudaGetSymbolAddress((void**)&BqaH, g_BqaH); cudaGetSymbolAddress((void**)&BqaL, g_BqaL);
    cudaGetSymbolAddress((void**)&BqbH, g_BqbH); cudaGetSymbolAddress((void**)&BqbL, g_BqbL);
    cudaGetSymbolAddress((void**)&BkaH, g_BkaH); cudaGetSymbolAddress((void**)&BkaL, g_BkaL);
    cudaGetSymbolAddress((void**)&BkbH, g_BkbH); cudaGetSymbolAddress((void**)&BkbL, g_BkbL);
    cudaGetSymbolAddress((void**)&BowH, g_BowH); cudaGetSymbolAddress((void**)&BowL, g_BowL);

    cudaFuncSetAttribute(flash_kernel,
                         cudaFuncAttributeMaxDynamicSharedMemorySize,
                         (int)FLASH_SMEM_BYTES);

    static cudaStream_t sA = nullptr, sB = nullptr;
    static cudaEvent_t evRoot, evA, evW1, evW2, evKV;
    if (!sA) {
        cudaStreamCreateWithFlags(&sA, cudaStreamNonBlocking);
        cudaStreamCreateWithFlags(&sB, cudaStreamNonBlocking);
        cudaEventCreateWithFlags(&evRoot, cudaEventDisableTiming);
        cudaEventCreateWithFlags(&evA, cudaEventDisableTiming);
        cudaEventCreateWithFlags(&evW1, cudaEventDisableTiming);
        cudaEventCreateWithFlags(&evW2, cudaEventDisableTiming);
        cudaEventCreateWithFlags(&evKV, cudaEventDisableTiming);
    }

    // fork
    cudaEventRecord(evRoot, 0);
    cudaStreamWaitEvent(sA, evRoot, 0);
    cudaStreamWaitEvent(sB, evRoot, 0);

    // main stream: q chain (R8 proven ordering)
    convB_kernel<<<6144, 256>>>(q_a_w, BqaH, BqaL, QR, HID);
    convA_kernel<<<8192, 256>>>(hs, AhsH, AhsL, HID);
    cudaEventRecord(evA, 0);
    gemm_fr_kernel<<<dim3(12, 16), 256>>>(AhsH, AhsL, BqaH, BqaL, p_qa, QR, HID);
    rmsnormA_kernel<<<S_LEN, 256>>>(p_qa, q_a_ln_w, AqaH, AqaL, QR, QR);

    // sA: kv chain
    convB_kernel<<<2560, 256, 0, sA>>>(kv_a_w, BkaH, BkaL, KVR + DR, HID);
    convB_kernel<<<4096, 256, 0, sA>>>(kv_b_w, BkbH, BkbL, NH * (DN + DV), KVR);
    cudaStreamWaitEvent(sA, evA, 0);
    gemm_fr_kernel<<<dim3(5, 16), 256, 0, sA>>>(AhsH, AhsL, BkaH, BkaL, p_kva,
                                                KVR + DR, HID);
    rmsnormA_kernel<<<S_LEN, 256, 0, sA>>>(p_kva, kv_a_ln_w, AkvH, AkvL,
                                           KVR + DR, KVR);
    gemm_fr_kernel<<<dim3(32, 16), 256, 0, sA>>>(AkvH, AkvL, BkbH, BkbL, p_kvb,
                                                 NH * (DN + DV), KVR);
    cudaEventRecord(evKV, sA);

    // sB: remaining weight conversions
    convB_kernel<<<9216, 256, 0, sB>>>(q_b_w, BqbH, BqbL, NH * DQK, QR);
    cudaEventRecord(evW1, sB);
    convB_kernel<<<8192, 256, 0, sB>>>(o_w, BowH, BowL, HID, HID);
    cudaEventRecord(evW2, sB);

    // join and finish on main stream
    cudaStreamWaitEvent(0, evW1, 0);
    gemm_fr_kernel<<<dim3(24, 16), 256>>>(AqaH, AqaL, BqbH, BqbL, p_q, NH * DQK, QR);
    cudaStreamWaitEvent(0, evKV, 0);
    assemble_kernel<<<dim3(S_LEN / 2, NH), 256>>>(pos_ids);
    flash_kernel<<<128, 256, FLASH_SMEM_BYTES>>>();
    cudaStreamWaitEvent(0, evW2, 0);
    gemm_fr_kernel<<<dim3(16, 16), 256>>>(AatH, AatL, BowH, BowL, out, HID, HID);
}

// round 14
// speedup vs baseline: 1.0136x; 1.0136x over previous
#include <cuda_runtime.h>
#include <cuda_fp16.h>
#include <cstdint>

constexpr int S_LEN = 2048, HID = 2048, NH = 16, QR = 1536, KVR = 512;
constexpr int DN = 128, DR = 64, DQK = 192, DV = 128;
constexpr float EPS = 1e-6f;

__device__ float g_qa [S_LEN * QR];
__device__ float g_q  [S_LEN * NH * DQK];
__device__ float g_kva[S_LEN * (KVR + DR)];

__device__ unsigned g_Qh[NH * (S_LEN/16) * 12 * 128];
__device__ unsigned g_Ql[NH * (S_LEN/16) * 12 * 128];
__device__ unsigned g_Kh[NH * (S_LEN/8)  * 12 * 64];
__device__ unsigned g_Kl[NH * (S_LEN/8)  * 12 * 64];
__device__ unsigned g_Vh[NH * (S_LEN/16) * 16 * 64];
__device__ unsigned g_Vl[NH * (S_LEN/16) * 16 * 64];

__device__ unsigned g_AhsH [2097152], g_AhsL [2097152];
__device__ unsigned g_AqaH [1572864], g_AqaL [1572864];
__device__ unsigned g_AkvH [524288],  g_AkvL [524288];
__device__ unsigned g_AatH [2097152], g_AatL [2097152];
__device__ unsigned g_BqaH [1572864], g_BqaL [1572864];
__device__ unsigned g_BqbH [2359296], g_BqbL [2359296];
__device__ unsigned g_BkaH [655360],  g_BkaL [655360];
__device__ unsigned g_BkbH [1048576], g_BkbL [1048576];
__device__ unsigned g_BowH [2097152], g_BowL [2097152];

__device__ __forceinline__ void split2(float x0, float x1,
                                       unsigned& hi, unsigned& lo) {
    __half h0 = __float2half_rn(x0), h1 = __float2half_rn(x1);
    __half l0 = __float2half_rn(x0 - __half2float(h0));
    __half l1 = __float2half_rn(x1 - __half2float(h1));
    hi = (unsigned)__half_as_ushort(h0) | ((unsigned)__half_as_ushort(h1) << 16);
    lo = (unsigned)__half_as_ushort(l0) | ((unsigned)__half_as_ushort(l1) << 16);
}

__device__ __forceinline__ void mma16(float* c, const uint4& a, const uint2& b) {
    asm volatile(
        "mma.sync.aligned.m16n8k16.row.col.f32.f16.f16.f32 "
        "{%0,%1,%2,%3}, {%4,%5,%6,%7}, {%8,%9}, {%0,%1,%2,%3};"
        : "+f"(c[0]), "+f"(c[1]), "+f"(c[2]), "+f"(c[3])
        : "r"(a.x), "r"(a.y), "r"(a.z), "r"(a.w), "r"(b.x), "r"(b.y));
}

__device__ __forceinline__ void cpa16(uint32_t dst, const void* src) {
    asm volatile("cp.async.cg.shared.global [%0], [%1], 16;"
                 :: "r"(dst), "l"(src) : "memory");
}

// ---------------------------------------------------------------------------
__global__ void __launch_bounds__(256) convA_kernel(
    const float* __restrict__ X, unsigned* __restrict__ Ph,
    unsigned* __restrict__ Pl, int K)
{
    size_t id = (size_t)blockIdx.x * 256 + threadIdx.x;
    int m = (int)(id / (K >> 1));
    int d = (int)(id % (K >> 1)) * 2;
    float2 v = *(const float2*)&X[(size_t)m * K + d];
    unsigned hi, lo; split2(v.x, v.y, hi, lo);
    size_t off = ((size_t)(m >> 4) * (K >> 4) + (d >> 4)) * 128
               + ((m & 7) * 4 + ((d & 7) >> 1)) * 4
               + ((d >> 3) & 1) * 2 + ((m >> 3) & 1);
    Ph[off] = hi; Pl[off] = lo;
}

__global__ void __launch_bounds__(256) convB_kernel(
    const float* __restrict__ W, unsigned* __restrict__ Ph,
    unsigned* __restrict__ Pl, int N, int K)
{
    size_t id = (size_t)blockIdx.x * 256 + threadIdx.x;
    int n = (int)(id / (K >> 1));
    int d = (int)(id % (K >> 1)) * 2;
    float v0 = 0.f, v1 = 0.f;
    if (n < N) { float2 v = *(const float2*)&W[(size_t)n * K + d]; v0 = v.x; v1 = v.y; }
    unsigned hi, lo; split2(v0, v1, hi, lo);
    size_t off = ((size_t)(n >> 3) * (K >> 4) + (d >> 4)) * 64
               + ((n & 7) * 4 + ((d & 7) >> 1)) * 2 + ((d >> 3) & 1);
    Ph[off] = hi; Pl[off] = lo;
}

// ---------------------------------------------------------------------------
// Shared GEMM mainloop: accumulates 128x128 tile; epilogue differs per kernel.
// ---------------------------------------------------------------------------
struct GemmCtx {
    int tid, lane, warp, wm, wn;
    size_t aS0, aS1, bS0, bS1;
    int aD0, aD1, bD0, bD1;
};

__device__ __forceinline__ void gemm_main(
    const unsigned* __restrict__ Ah, const unsigned* __restrict__ Al,
    const unsigned* __restrict__ Bh, const unsigned* __restrict__ Bl,
    int K, unsigned (*sm)[4][2048], float acc[4][4][4], GemmCtx& cx)
{
    const int tid = threadIdx.x, lane = tid & 31, warp = tid >> 5;
    cx.tid = tid; cx.lane = lane; cx.warp = warp;
    cx.wm = warp >> 2; cx.wn = warp & 3;
    const int m0t = blockIdx.y * 8, n0t = blockIdx.x * 16;
    const int KT = K >> 4;

    const int f0 = tid, f1 = tid + 256;
    const int aM0 = f0 >> 6, aK0 = (f0 & 63) >> 5, aW0 = f0 & 31;
    const int aM1 = f1 >> 6, aK1 = (f1 & 63) >> 5, aW1 = f1 & 31;
    cx.aS0 = ((size_t)(m0t + aM0) * KT + aK0) * 128 + aW0 * 4;
    cx.aS1 = ((size_t)(m0t + aM1) * KT + aK1) * 128 + aW1 * 4;
    cx.aD0 = (aM0 * 2 + aK0) * 128 + aW0 * 4;
    cx.aD1 = (aM1 * 2 + aK1) * 128 + aW1 * 4;
    const int bN0 = f0 >> 5, bK0 = (f0 & 31) >> 4, bW0 = f0 & 15;
    const int bN1 = f1 >> 5, bK1 = (f1 & 31) >> 4, bW1 = f1 & 15;
    cx.bS0 = ((size_t)(n0t + bN0) * KT + bK0) * 64 + bW0 * 4;
    cx.bS1 = ((size_t)(n0t + bN1) * KT + bK1) * 64 + bW1 * 4;
    cx.bD0 = (bN0 * 2 + bK0) * 64 + bW0 * 4;
    cx.bD1 = (bN1 * 2 + bK1) * 64 + bW1 * 4;

    const uint32_t sb = (uint32_t)__cvta_generic_to_shared(&sm[0][0][0]);
    auto issue = [&](int c, int st) {
        const size_t ao = (size_t)c * 256, bo = (size_t)c * 128;
        const uint32_t s0 = sb + (uint32_t)(st * 4) * 8192;
        cpa16(s0 + cx.aD0 * 4,          Ah + cx.aS0 + ao);
        cpa16(s0 + cx.aD1 * 4,          Ah + cx.aS1 + ao);
        cpa16(s0 + 8192  + cx.aD0 * 4,  Al + cx.aS0 + ao);
        cpa16(s0 + 8192  + cx.aD1 * 4,  Al + cx.aS1 + ao);
        cpa16(s0 + 16384 + cx.bD0 * 4,  Bh + cx.bS0 + bo);
        cpa16(s0 + 16384 + cx.bD1 * 4,  Bh + cx.bS1 + bo);
        cpa16(s0 + 24576 + cx.bD0 * 4,  Bl + cx.bS0 + bo);
        cpa16(s0 + 24576 + cx.bD1 * 4,  Bl + cx.bS1 + bo);
        asm volatile("cp.async.commit_group;" ::: "memory");
    };

    #pragma unroll
    for (int i = 0; i < 4; i++)
        #pragma unroll
        for (int j = 0; j < 4; j++)
            #pragma unroll
            for (int r = 0; r < 4; r++) acc[i][j][r] = 0.f;

    const int nc = K >> 5;
    issue(0, 0);

    for (int c = 0; c < nc; c++) {
        const int s = c & 1;
        if (c + 1 < nc) {
            issue(c + 1, s ^ 1);
            asm volatile("cp.async.wait_group 1;" ::: "memory");
        } else {
            asm volatile("cp.async.wait_group 0;" ::: "memory");
        }
        __syncthreads();

        #pragma unroll
        for (int kt = 0; kt < 2; kt++) {
            uint4 a_h[4], a_l[4];
            #pragma unroll
            for (int i = 0; i < 4; i++) {
                int off = ((cx.wm * 4 + i) * 2 + kt) * 128 + lane * 4;
                a_h[i] = *(const uint4*)&sm[s][0][off];
                a_l[i] = *(const uint4*)&sm[s][1][off];
            }
            #pragma unroll
            for (int jp = 0; jp < 2; jp++) {
                uint2 b_h[2], b_l[2];
                #pragma unroll
                for (int jj = 0; jj < 2; jj++) {
                    int off = ((cx.wn * 4 + jp * 2 + jj) * 2 + kt) * 64 + lane * 2;
                    b_h[jj] = *(const uint2*)&sm[s][2][off];
                    b_l[jj] = *(const uint2*)&sm[s][3][off];
                }
                #pragma unroll
                for (int jj = 0; jj < 2; jj++)
                    #pragma unroll
                    for (int i = 0; i < 4; i++)
                        mma16(acc[i][jp*2+jj], a_h[i], b_h[jj]);
                #pragma unroll
                for (int jj = 0; jj < 2; jj++)
                    #pragma unroll
                    for (int i = 0; i < 4; i++)
                        mma16(acc[i][jp*2+jj], a_h[i], b_l[jj]);
                #pragma unroll
                for (int jj = 0; jj < 2; jj++)
                    #pragma unroll
                    for (int i = 0; i < 4; i++)
                        mma16(acc[i][jp*2+jj], a_l[i], b_h[jj]);
            }
        }
        __syncthreads();
    }
}

// Generic GEMM: fp32 C output
__global__ void __launch_bounds__(256, 2) gemm_fr_kernel(
    const unsigned* __restrict__ Ah, const unsigned* __restrict__ Al,
    const unsigned* __restrict__ Bh, const unsigned* __restrict__ Bl,
    float* __restrict__ C, int N, int K)
{
    __shared__ unsigned sm[2][4][2048];
    float acc[4][4][4];
    GemmCtx cx;
    gemm_main(Ah, Al, Bh, Bl, K, sm, acc, cx);

    const int g = cx.lane >> 2, q = cx.lane & 3;
    const int m0 = blockIdx.y * 128, n0 = blockIdx.x * 128;
    #pragma unroll
    for (int i = 0; i < 4; i++) {
        const int row = m0 + cx.wm * 64 + i * 16 + g;
        #pragma unroll
        for (int j = 0; j < 4; j++) {
            const int colb = n0 + cx.wn * 32 + j * 8;
            if (colb < N) {
                const int col = colb + 2 * q;
                *(float2*)&C[(size_t)row * N + col] =
                    make_float2(acc[i][j][0], acc[i][j][1]);
                *(float2*)&C[(size_t)(row + 8) * N + col] =
                    make_float2(acc[i][j][2], acc[i][j][3]);
            }
        }
    }
}

// Specialized kv_b GEMM: N=4096, writes K-nope / V fragment planes directly.
// Even blockIdx.x -> K half of a head (d<128); odd -> V half.
__global__ void __launch_bounds__(256, 2) gemm_kvb_kernel(
    const unsigned* __restrict__ Ah, const unsigned* __restrict__ Al,
    const unsigned* __restrict__ Bh, const unsigned* __restrict__ Bl,
    int K)
{
    __shared__ unsigned sm[2][4][2048];
    float acc[4][4][4];
    GemmCtx cx;
    gemm_main(Ah, Al, Bh, Bl, K, sm, acc, cx);

    const int g = cx.lane >> 2, q = cx.lane & 3;
    const int m0 = blockIdx.y * 128, n0 = blockIdx.x * 128;
    const int h = n0 >> 8;
    const bool isK = ((n0 & 255) == 0);

    if (isK) {
        #pragma unroll
        for (int i = 0; i < 4; i++) {
            #pragma unroll
            for (int j = 0; j < 4; j++) {
                const int col = n0 + cx.wn * 32 + j * 8 + 2 * q;
                const int d = col & 255;                      // < 128, even
                #pragma unroll
                for (int half = 0; half < 2; half++) {
                    const int t = m0 + cx.wm * 64 + i * 16 + g + half * 8;
                    unsigned hi, lo;
                    split2(acc[i][j][half*2], acc[i][j][half*2+1], hi, lo);
                    size_t off = ((size_t)(h * 256 + (t >> 3)) * 12 + (d >> 4)) * 64
                               + ((t & 7) * 4 + ((d & 7) >> 1)) * 2 + ((d >> 3) & 1);
                    g_Kh[off] = hi; g_Kl[off] = lo;
                }
            }
        }
    } else {
        #pragma unroll
        for (int i = 0; i < 4; i++) {
            #pragma unroll
            for (int j = 0; j < 4; j++) {
                float nxt[4];
                #pragma unroll
                for (int r = 0; r < 4; r++)
                    nxt[r] = __shfl_down_sync(0xffffffffu, acc[i][j][r], 4);
                if ((g & 1) == 0) {                           // even row -> t0
                    const int col = n0 + cx.wn * 32 + j * 8 + 2 * q;
                    const int dbase = (col & 255) - 128;
                    #pragma unroll
                    for (int half = 0; half < 2; half++) {
                        const int t0 = m0 + cx.wm * 64 + i * 16 + g + half * 8;
                        #pragma unroll
                        for (int dd = 0; dd < 2; dd++) {
                            const int d = dbase + dd;
                            unsigned hi, lo;
                            split2(acc[i][j][half*2+dd], nxt[half*2+dd], hi, lo);
                            size_t off = ((size_t)(h*128 + (t0>>4))*16 + (d>>3))*64
                                       + ((d&7)*4 + ((t0&7)>>1))*2 + ((t0>>3)&1);
                            g_Vh[off] = hi; g_Vl[off] = lo;
                        }
                    }
                }
            }
        }
    }
}

// ---------------------------------------------------------------------------
__global__ void __launch_bounds__(256) rmsnormA_kernel(
    const float* __restrict__ x, const float* __restrict__ w,
    unsigned* __restrict__ Ph, unsigned* __restrict__ Pl, int ld, int n)
{
    const int row = blockIdx.x;
    const float* xr = x + (size_t)row * ld;
    float s = 0.f;
    for (int i = threadIdx.x; i < n; i += 256) { float v = xr[i]; s += v * v; }
    __shared__ float red[8];
    #pragma unroll
    for (int o = 16; o; o >>= 1) s += __shfl_xor_sync(0xffffffffu, s, o);
    if ((threadIdx.x & 31) == 0) red[threadIdx.x >> 5] = s;
    __syncthreads();
    if (threadIdx.x < 32) {
        float v = (threadIdx.x < 8) ? red[threadIdx.x] : 0.f;
        #pragma unroll
        for (int o = 4; o; o >>= 1) v += __shfl_xor_sync(0xffffffffu, v, o);
        if (threadIdx.x == 0) red[0] = v;
    }
    __syncthreads();
    const float r = rsqrtf(red[0] / (float)n + EPS);
    for (int dp = threadIdx.x; dp < (n >> 1); dp += 256) {
        int d = dp * 2;
        float v0 = w[d] * xr[d] * r, v1 = w[d + 1] * xr[d + 1] * r;
        unsigned hi, lo; split2(v0, v1, hi, lo);
        size_t off = ((size_t)(row >> 4) * (n >> 4) + (d >> 4)) * 128
                   + ((row & 7) * 4 + ((d & 7) >> 1)) * 4
                   + ((d >> 3) & 1) * 2 + ((row >> 3) & 1);
        Ph[off] = hi; Pl[off] = lo;
    }
}

// ---------------------------------------------------------------------------
// Assemble: Q (RoPE) + K-rope part only. Grid (S_LEN/2, NH).
// ---------------------------------------------------------------------------
__global__ void __launch_bounds__(256) assemble_kernel(
    const void* __restrict__ pos_ids)
{
    const int b = blockIdx.x, t0 = 2 * b, tid = threadIdx.x;
    const int h = blockIdx.y;
    __shared__ float cs[2][DR], sn[2][DR], kr[2][DR];
    __shared__ float posv[2];

    if (tid < 2) {
        const int* p32 = (const int*)pos_ids;
        int t = t0 + tid;
        long long pv = (p32[1] == 0) ? ((const long long*)pos_ids)[t]
                                     : (long long)p32[t];
        posv[tid] = (float)pv;
    }
    __syncthreads();
    if (tid < 128) {
        int tok = tid >> 6, i = tid & 63, j = i & 31;
        double e = -((double)(2 * j) / 64.0) * 13.287712379549449;
        float ang = posv[tok] * (float)exp2(e);
        cs[tok][i] = cosf(ang); sn[tok][i] = sinf(ang);
    }
    __syncthreads();
    if (tid < 128) {
        int tok = tid >> 6, i = tid & 63;
        const float* kx = g_kva + (size_t)(t0 + tok) * (KVR + DR) + KVR;
        kr[tok][i] = (i < 32) ? kx[i] * cs[tok][i] - kx[i + 32] * sn[tok][i]
                              : kx[i] * cs[tok][i] + kx[i - 32] * sn[tok][i];
    }
    __syncthreads();

    const float scale = rsqrtf((float)DQK);

    if (tid < 192) {                                  // Q (all 192 dims)
        int tok = tid / 96, pp = tid % 96, d = 2 * pp;
        int t = t0 + tok;
        const float* qrow = g_q + (size_t)t * (NH * DQK) + h * DQK;
        float v0, v1;
        if (d < DN) { v0 = qrow[d]; v1 = qrow[d + 1]; }
        else {
            int i = d - DN;
            if (i < 32) {
                v0 = qrow[d]   * cs[tok][i]   - qrow[d + 32] * sn[tok][i];
                v1 = qrow[d+1] * cs[tok][i+1] - qrow[d + 33] * sn[tok][i+1];
            } else {
                v0 = qrow[d]   * cs[tok][i]   + qrow[d - 32] * sn[tok][i];
                v1 = qrow[d+1] * cs[tok][i+1] + qrow[d - 31] * sn[tok][i+1];
            }
        }
        v0 *= scale; v1 *= scale;
        unsigned hi, lo; split2(v0, v1, hi, lo);
        int mt = t >> 4, r = t & 15;
        size_t off = ((size_t)(h * 128 + mt) * 12 + (d >> 4)) * 128
                   + ((r & 7) * 4 + ((d & 7) >> 1)) * 4
                   + (((d >> 3) & 1) * 2 + (r >> 3));
        g_Qh[off] = hi; g_Ql[off] = lo;
    }
    if (tid < 64) {                                   // K-rope (d in [128,192))
        int tok = tid >> 5, i2 = (tid & 31) * 2;      // i2 = 0..62 even
        int d = DN + i2;
        int t = t0 + tok;
        float v0 = kr[tok][i2], v1 = kr[tok][i2 + 1];
        unsigned hi, lo; split2(v0, v1, hi, lo);
        int nt = t >> 3, n = t & 7;
        size_t off = ((size_t)(h * 256 + nt) * 12 + (d >> 4)) * 64
                   + (n * 4 + ((d & 7) >> 1)) * 2 + ((d >> 3) & 1);
        g_Kh[off] = hi; g_Kl[off] = lo;
    }
}

// ---------------------------------------------------------------------------
// Flash attention (R8 proven 256-CTA heavy-first version)
// ---------------------------------------------------------------------------
constexpr int FL_STAGE = 20480;
constexpr size_t FLASH_SMEM_BYTES = (12288 + 2 * FL_STAGE) * 4;

__global__ void __launch_bounds__(256) flash_kernel()
{
    const int bx = blockIdx.x;
    const int qt = 15 - (bx >> 4);
    const int h  = bx & 15;
    const int q0 = qt * 128;
    const int tid = threadIdx.x, wid = tid >> 5, lane = tid & 31;
    const int g = lane >> 2, q = lane & 3;

    extern __shared__ unsigned smu[];
    unsigned* QL = smu;
    const uint32_t sb = (uint32_t)__cvta_generic_to_shared(smu);

    uint4 qh[12];
    {
        const size_t qbase = (size_t)(h * 128 + qt * 8 + wid) * 12 * 128;
        #pragma unroll
        for (int kt = 0; kt < 12; kt++)
            qh[kt] = *(const uint4*)&g_Qh[qbase + kt * 128 + lane * 4];
        const uint4* gl = (const uint4*)(g_Ql + (size_t)(h * 128 + qt * 8) * 1536);
        uint4* dl = (uint4*)QL;
        #pragma unroll
        for (int j = 0; j < 12; j++) dl[j * 256 + tid] = gl[j * 256 + tid];
    }

    const int niter = 2 * (qt + 1);
    const int wrow0 = q0 + wid * 16;

    auto issue = [&](int it, int st) {
        const uint4* gkh = (const uint4*)(g_Kh + (size_t)(h * 256 + it * 8) * 768);
        const uint4* gkl = (const uint4*)(g_Kl + (size_t)(h * 256 + it * 8) * 768);
        const uint4* gvh = (const uint4*)(g_Vh + (size_t)(h * 128 + it * 4) * 1024);
        const uint4* gvl = (const uint4*)(g_Vl + (size_t)(h * 128 + it * 4) * 1024);
        const uint32_t s0 = sb + (12288u + (uint32_t)st * FL_STAGE) * 4;
        #pragma unroll
        for (int j = 0; j < 6; j++) {
            cpa16(s0 +         (j * 256 + tid) * 16, gkh + j * 256 + tid);
            cpa16(s0 + 24576 + (j * 256 + tid) * 16, gkl + j * 256 + tid);
        }
        #pragma unroll
        for (int j = 0; j < 4; j++) {
            cpa16(s0 + 49152 + (j * 256 + tid) * 16, gvh + j * 256 + tid);
            cpa16(s0 + 65536 + (j * 256 + tid) * 16, gvl + j * 256 + tid);
        }
        asm volatile("cp.async.commit_group;" ::: "memory");
    };

    float O[16][4];
    #pragma unroll
    for (int nt = 0; nt < 16; nt++)
        #pragma unroll
        for (int r = 0; r < 4; r++) O[nt][r] = 0.f;
    float m0 = -1e30f, m1 = -1e30f, l0 = 0.f, l1 = 0.f;

    issue(0, 0);

    for (int it = 0; it < niter; it++) {
        const int s = it & 1;
        const int k0 = it * 64;
        if (it + 1 < niter) {
            issue(it + 1, s ^ 1);
            asm volatile("cp.async.wait_group 1;" ::: "memory");
        } else {
            asm volatile("cp.async.wait_group 0;" ::: "memory");
        }
        __syncthreads();

        unsigned* KHs = smu + 12288 + s * FL_STAGE;
        unsigned* KLs = KHs + 6144;
        unsigned* VHs = KHs + 12288;
        unsigned* VLs = KHs + 16384;

        if (k0 <= wrow0 + 15) {
            float S[8][4];
            #pragma unroll
            for (int nt = 0; nt < 8; nt++)
                #pragma unroll
                for (int r = 0; r < 4; r++) S[nt][r] = 0.f;

            #pragma unroll
            for (int kt = 0; kt < 12; kt++) {
                uint4 qhv = qh[kt];
                uint4 qlv = *(const uint4*)&QL[wid * 1536 + kt * 128 + lane * 4];
                #pragma unroll
                for (int nt = 0; nt < 8; nt++) {
                    uint2 kh = *(const uint2*)&KHs[(nt * 12 + kt) * 64 + lane * 2];
                    uint2 kl = *(const uint2*)&KLs[(nt * 12 + kt) * 64 + lane * 2];
                    mma16(S[nt], qhv, kh);
                    mma16(S[nt], qhv, kl);
                    mma16(S[nt], qlv, kh);
                }
            }

            if (k0 + 63 > wrow0) {
                const int row0 = wrow0 + g, row1 = row0 + 8;
                #pragma unroll
                for (int nt = 0; nt < 8; nt++) {
                    int col = k0 + nt * 8 + 2 * q;
                    if (col     > row0) S[nt][0] = -1e30f;
                    if (col + 1 > row0) S[nt][1] = -1e30f;
                    if (col     > row1) S[nt][2] = -1e30f;
                    if (col + 1 > row1) S[nt][3] = -1e30f;
                }
            }

            float rm0 = -1e30f, rm1 = -1e30f;
            #pragma unroll
            for (int nt = 0; nt < 8; nt++) {
                rm0 = fmaxf(rm0, fmaxf(S[nt][0], S[nt][1]));
                rm1 = fmaxf(rm1, fmaxf(S[nt][2], S[nt][3]));
            }
            rm0 = fmaxf(rm0, __shfl_xor_sync(0xffffffffu, rm0, 1));
            rm0 = fmaxf(rm0, __shfl_xor_sync(0xffffffffu, rm0, 2));
            rm1 = fmaxf(rm1, __shfl_xor_sync(0xffffffffu, rm1, 1));
            rm1 = fmaxf(rm1, __shfl_xor_sync(0xffffffffu, rm1, 2));

            float mn0 = fmaxf(m0, rm0), mn1 = fmaxf(m1, rm1);
            float a0 = __expf(m0 - mn0), a1 = __expf(m1 - mn1);

            unsigned PH[8], PL[8], P8H[8], P8L[8];
            float s0 = 0.f, s1 = 0.f;
            #pragma unroll
            for (int nt = 0; nt < 8; nt++) {
                float p00 = __expf(S[nt][0] - mn0);
                float p01 = __expf(S[nt][1] - mn0);
                float p10 = __expf(S[nt][2] - mn1);
                float p11 = __expf(S[nt][3] - mn1);
                s0 += p00 + p01; s1 += p10 + p11;
                split2(p00, p01, PH[nt], PL[nt]);
                split2(p10, p11, P8H[nt], P8L[nt]);
            }
            s0 += __shfl_xor_sync(0xffffffffu, s0, 1);
            s0 += __shfl_xor_sync(0xffffffffu, s0, 2);
            s1 += __shfl_xor_sync(0xffffffffu, s1, 1);
            s1 += __shfl_xor_sync(0xffffffffu, s1, 2);

            l0 = l0 * a0 + s0; l1 = l1 * a1 + s1;
            m0 = mn0; m1 = mn1;

            #pragma unroll
            for (int nt = 0; nt < 16; nt++) {
                O[nt][0] *= a0; O[nt][1] *= a0;
                O[nt][2] *= a1; O[nt][3] *= a1;
            }

            #pragma unroll
            for (int kt2 = 0; kt2 < 4; kt2++) {
                uint4 ah = make_uint4(PH[2*kt2], P8H[2*kt2], PH[2*kt2+1], P8H[2*kt2+1]);
                uint4 al = make_uint4(PL[2*kt2], P8L[2*kt2], PL[2*kt2+1], P8L[2*kt2+1]);
                #pragma unroll
                for (int nt = 0; nt < 16; nt++) {
                    uint2 vh = *(const uint2*)&VHs[(kt2 * 16 + nt) * 64 + lane * 2];
                    uint2 vl = *(const uint2*)&VLs[(kt2 * 16 + nt) * 64 + lane * 2];
                    mma16(O[nt], ah, vh);
                    mma16(O[nt], ah, vl);
                    mma16(O[nt], al, vh);
                }
            }
        }
        __syncthreads();
    }

    const float inv0 = __fdividef(1.f, l0), inv1 = __fdividef(1.f, l1);
    const int row0 = wrow0 + g;
    const size_t baseRow = (size_t)(row0 >> 4) * 128;
    #pragma unroll
    for (int nt = 0; nt < 16; nt++) {
        const int ktv = h * 8 + (nt >> 1);
        const size_t off = (baseRow + ktv) * 128 + lane * 4 + (nt & 1) * 2;
        unsigned hi, lo;
        split2(O[nt][0] * inv0, O[nt][1] * inv0, hi, lo);
        g_AatH[off] = hi; g_AatL[off] = lo;
        split2(O[nt][2] * inv1, O[nt][3] * inv1, hi, lo);
        g_AatH[off + 1] = hi; g_AatL[off + 1] = lo;
    }
}

// ---------------------------------------------------------------------------
extern "C" void kernel_launch(void* const* d_in, const int* in_sizes, int n_in,
                              void* d_out, int out_size)
{
    const float* hs       = (const float*)d_in[0];
    const void*  pos_ids  = d_in[1];
    const float* q_a_w    = (const float*)d_in[2];
    const float* q_a_ln_w = (const float*)d_in[3];
    const float* q_b_w    = (const float*)d_in[4];
    const float* kv_a_w   = (const float*)d_in[5];
    const float* kv_a_ln_w= (const float*)d_in[6];
    const float* kv_b_w   = (const float*)d_in[7];
    const float* o_w      = (const float*)d_in[8];
    float*       out      = (float*)d_out;

    float *p_qa, *p_q, *p_kva;
    cudaGetSymbolAddress((void**)&p_qa,  g_qa);
    cudaGetSymbolAddress((void**)&p_q,   g_q);
    cudaGetSymbolAddress((void**)&p_kva, g_kva);
    unsigned *AhsH,*AhsL,*AqaH,*AqaL,*AkvH,*AkvL,*AatH,*AatL;
    unsigned *BqaH,*BqaL,*BqbH,*BqbL,*BkaH,*BkaL,*BkbH,*BkbL,*BowH,*BowL;
    cudaGetSymbolAddress((void**)&AhsH, g_AhsH); cudaGetSymbolAddress((void**)&AhsL, g_AhsL);
    cudaGetSymbolAddress((void**)&AqaH, g_AqaH); cudaGetSymbolAddress((void**)&AqaL, g_AqaL);
    cudaGetSymbolAddress((void**)&AkvH, g_AkvH); cudaGetSymbolAddress((void**)&AkvL, g_AkvL);
    cudaGetSymbolAddress((void**)&AatH, g_AatH); cudaGetSymbolAddress((void**)&AatL, g_AatL);
    cudaGetSymbolAddress((void**)&BqaH, g_BqaH); cudaGetSymbolAddress((void**)&BqaL, g_BqaL);
    cudaGetSymbolAddress((void**)&BqbH, g_BqbH); cudaGetSymbolAddress((void**)&BqbL, g_BqbL);
    cudaGetSymbolAddress((void**)&BkaH, g_BkaH); cudaGetSymbolAddress((void**)&BkaL, g_BkaL);
    cudaGetSymbolAddress((void**)&BkbH, g_BkbH); cudaGetSymbolAddress((void**)&BkbL, g_BkbL);
    cudaGetSymbolAddress((void**)&BowH, g_BowH); cudaGetSymbolAddress((void**)&BowL, g_BowL);

    cudaFuncSetAttribute(flash_kernel,
                         cudaFuncAttributeMaxDynamicSharedMemorySize,
                         (int)FLASH_SMEM_BYTES);

    static cudaStream_t sA = nullptr, sB = nullptr;
    static cudaEvent_t evRoot, evA, evW1, evW2, evKV;
    if (!sA) {
        cudaStreamCreateWithFlags(&sA, cudaStreamNonBlocking);
        cudaStreamCreateWithFlags(&sB, cudaStreamNonBlocking);
        cudaEventCreateWithFlags(&evRoot, cudaEventDisableTiming);
        cudaEventCreateWithFlags(&evA, cudaEventDisableTiming);
        cudaEventCreateWithFlags(&evW1, cudaEventDisableTiming);
        cudaEventCreateWithFlags(&evW2, cudaEventDisableTiming);
        cudaEventCreateWithFlags(&evKV, cudaEventDisableTiming);
    }

    // fork
    cudaEventRecord(evRoot, 0);
    cudaStreamWaitEvent(sA, evRoot, 0);
    cudaStreamWaitEvent(sB, evRoot, 0);

    // main stream: q chain (R8 proven ordering)
    convB_kernel<<<6144, 256>>>(q_a_w, BqaH, BqaL, QR, HID);
    convA_kernel<<<8192, 256>>>(hs, AhsH, AhsL, HID);
    cudaEventRecord(evA, 0);
    gemm_fr_kernel<<<dim3(12, 16), 256>>>(AhsH, AhsL, BqaH, BqaL, p_qa, QR, HID);
    rmsnormA_kernel<<<S_LEN, 256>>>(p_qa, q_a_ln_w, AqaH, AqaL, QR, QR);

    // sA: kv chain (kv_b writes K/V fragments directly)
    convB_kernel<<<2560, 256, 0, sA>>>(kv_a_w, BkaH, BkaL, KVR + DR, HID);
    convB_kernel<<<4096, 256, 0, sA>>>(kv_b_w, BkbH, BkbL, NH * (DN + DV), KVR);
    cudaStreamWaitEvent(sA, evA, 0);
    gemm_fr_kernel<<<dim3(5, 16), 256, 0, sA>>>(AhsH, AhsL, BkaH, BkaL, p_kva,
                                                KVR + DR, HID);
    rmsnormA_kernel<<<S_LEN, 256, 0, sA>>>(p_kva, kv_a_ln_w, AkvH, AkvL,
                                           KVR + DR, KVR);
    gemm_kvb_kernel<<<dim3(32, 16), 256, 0, sA>>>(AkvH, AkvL, BkbH, BkbL, KVR);
    cudaEventRecord(evKV, sA);

    // sB: remaining weight conversions
    convB_kernel<<<9216, 256, 0, sB>>>(q_b_w, BqbH, BqbL, NH * DQK, QR);
    cudaEventRecord(evW1, sB);
    convB_kernel<<<8192, 256, 0, sB>>>(o_w, BowH, BowL, HID, HID);
    cudaEventRecord(evW2, sB);

    // join and finish on main stream
    cudaStreamWaitEvent(0, evW1, 0);
    gemm_fr_kernel<<<dim3(24, 16), 256>>>(AqaH, AqaL, BqbH, BqbL, p_q, NH * DQK, QR);
    cudaStreamWaitEvent(0, evKV, 0);
    assemble_kernel<<<dim3(S_LEN / 2, NH), 256>>>(pos_ids);
    flash_kernel<<<256, 256, FLASH_SMEM_BYTES>>>();
    cudaStreamWaitEvent(0, evW2, 0);
    gemm_fr_kernel<<<dim3(16, 16), 256>>>(AatH, AatL, BowH, BowL, out, HID, HID);
}

// round 15
// speedup vs baseline: 1.0196x; 1.0059x over previous
#include <cuda_runtime.h>
#include <cuda_fp16.h>
#include <cstdint>

constexpr int S_LEN = 2048, HID = 2048, NH = 16, QR = 1536, KVR = 512;
constexpr int DN = 128, DR = 64, DQK = 192, DV = 128;
constexpr float EPS = 1e-6f;

__device__ float g_qa   [S_LEN * QR];
__device__ float g_kva  [S_LEN * (KVR + DR)];
__device__ float g_kvb  [S_LEN * NH * (DN + DV)];
__device__ float g_qrope[S_LEN * NH * DR];          // pre-scaled rope dims of q

__device__ unsigned g_Qh[NH * (S_LEN/16) * 12 * 128];
__device__ unsigned g_Ql[NH * (S_LEN/16) * 12 * 128];
__device__ unsigned g_Kh[NH * (S_LEN/8)  * 12 * 64];
__device__ unsigned g_Kl[NH * (S_LEN/8)  * 12 * 64];
__device__ unsigned g_Vh[NH * (S_LEN/16) * 16 * 64];
__device__ unsigned g_Vl[NH * (S_LEN/16) * 16 * 64];

__device__ unsigned g_AhsH [2097152], g_AhsL [2097152];
__device__ unsigned g_AqaH [1572864], g_AqaL [1572864];
__device__ unsigned g_AkvH [524288],  g_AkvL [524288];
__device__ unsigned g_AatH [2097152], g_AatL [2097152];
__device__ unsigned g_BqaH [1572864], g_BqaL [1572864];
__device__ unsigned g_BqbH [2359296], g_BqbL [2359296];
__device__ unsigned g_BkaH [655360],  g_BkaL [655360];
__device__ unsigned g_BkbH [1048576], g_BkbL [1048576];
__device__ unsigned g_BowH [2097152], g_BowL [2097152];

__device__ __forceinline__ void split2(float x0, float x1,
                                       unsigned& hi, unsigned& lo) {
    __half h0 = __float2half_rn(x0), h1 = __float2half_rn(x1);
    __half l0 = __float2half_rn(x0 - __half2float(h0));
    __half l1 = __float2half_rn(x1 - __half2float(h1));
    hi = (unsigned)__half_as_ushort(h0) | ((unsigned)__half_as_ushort(h1) << 16);
    lo = (unsigned)__half_as_ushort(l0) | ((unsigned)__half_as_ushort(l1) << 16);
}

__device__ __forceinline__ void mma16(float* c, const uint4& a, const uint2& b) {
    asm volatile(
        "mma.sync.aligned.m16n8k16.row.col.f32.f16.f16.f32 "
        "{%0,%1,%2,%3}, {%4,%5,%6,%7}, {%8,%9}, {%0,%1,%2,%3};"
        : "+f"(c[0]), "+f"(c[1]), "+f"(c[2]), "+f"(c[3])
        : "r"(a.x), "r"(a.y), "r"(a.z), "r"(a.w), "r"(b.x), "r"(b.y));
}

__device__ __forceinline__ void cpa16(uint32_t dst, const void* src) {
    asm volatile("cp.async.cg.shared.global [%0], [%1], 16;"
                 :: "r"(dst), "l"(src) : "memory");
}

// Q fragment-plane offset for (head h, token t, dim pair base d)
__device__ __forceinline__ size_t qfrag_off(int h, int t, int d) {
    return ((size_t)(h * 128 + (t >> 4)) * 12 + (d >> 4)) * 128
         + (((t & 7) * 4 + ((d & 7) >> 1)) * 4)
         + (((d >> 3) & 1) * 2 + ((t >> 3) & 1));
}

// ---------------------------------------------------------------------------
__global__ void __launch_bounds__(256) convA_kernel(
    const float* __restrict__ X, unsigned* __restrict__ Ph,
    unsigned* __restrict__ Pl, int K)
{
    size_t id = (size_t)blockIdx.x * 256 + threadIdx.x;
    int m = (int)(id / (K >> 1));
    int d = (int)(id % (K >> 1)) * 2;
    float2 v = *(const float2*)&X[(size_t)m * K + d];
    unsigned hi, lo; split2(v.x, v.y, hi, lo);
    size_t off = ((size_t)(m >> 4) * (K >> 4) + (d >> 4)) * 128
               + ((m & 7) * 4 + ((d & 7) >> 1)) * 4
               + ((d >> 3) & 1) * 2 + ((m >> 3) & 1);
    Ph[off] = hi; Pl[off] = lo;
}

__global__ void __launch_bounds__(256) convB_kernel(
    const float* __restrict__ W, unsigned* __restrict__ Ph,
    unsigned* __restrict__ Pl, int N, int K)
{
    size_t id = (size_t)blockIdx.x * 256 + threadIdx.x;
    int n = (int)(id / (K >> 1));
    int d = (int)(id % (K >> 1)) * 2;
    float v0 = 0.f, v1 = 0.f;
    if (n < N) { float2 v = *(const float2*)&W[(size_t)n * K + d]; v0 = v.x; v1 = v.y; }
    unsigned hi, lo; split2(v0, v1, hi, lo);
    size_t off = ((size_t)(n >> 3) * (K >> 4) + (d >> 4)) * 64
               + ((n & 7) * 4 + ((d & 7) >> 1)) * 2 + ((d >> 3) & 1);
    Ph[off] = hi; Pl[off] = lo;
}

// ---------------------------------------------------------------------------
// Shared GEMM mainloop (R8 proven 2-stage form)
// ---------------------------------------------------------------------------
struct GemmCtx { int lane, wm, wn; };

__device__ __forceinline__ void gemm_main(
    const unsigned* __restrict__ Ah, const unsigned* __restrict__ Al,
    const unsigned* __restrict__ Bh, const unsigned* __restrict__ Bl,
    int K, unsigned (*sm)[4][2048], float acc[4][4][4], GemmCtx& cx)
{
    const int tid = threadIdx.x, lane = tid & 31, warp = tid >> 5;
    cx.lane = lane; cx.wm = warp >> 2; cx.wn = warp & 3;
    const int m0t = blockIdx.y * 8, n0t = blockIdx.x * 16;
    const int KT = K >> 4;

    const int f0 = tid, f1 = tid + 256;
    const int aM0 = f0 >> 6, aK0 = (f0 & 63) >> 5, aW0 = f0 & 31;
    const int aM1 = f1 >> 6, aK1 = (f1 & 63) >> 5, aW1 = f1 & 31;
    const size_t aS0 = ((size_t)(m0t + aM0) * KT + aK0) * 128 + aW0 * 4;
    const size_t aS1 = ((size_t)(m0t + aM1) * KT + aK1) * 128 + aW1 * 4;
    const int aD0 = (aM0 * 2 + aK0) * 128 + aW0 * 4;
    const int aD1 = (aM1 * 2 + aK1) * 128 + aW1 * 4;
    const int bN0 = f0 >> 5, bK0 = (f0 & 31) >> 4, bW0 = f0 & 15;
    const int bN1 = f1 >> 5, bK1 = (f1 & 31) >> 4, bW1 = f1 & 15;
    const size_t bS0 = ((size_t)(n0t + bN0) * KT + bK0) * 64 + bW0 * 4;
    const size_t bS1 = ((size_t)(n0t + bN1) * KT + bK1) * 64 + bW1 * 4;
    const int bD0 = (bN0 * 2 + bK0) * 64 + bW0 * 4;
    const int bD1 = (bN1 * 2 + bK1) * 64 + bW1 * 4;

    const uint32_t sb = (uint32_t)__cvta_generic_to_shared(&sm[0][0][0]);
    auto issue = [&](int c, int st) {
        const size_t ao = (size_t)c * 256, bo = (size_t)c * 128;
        const uint32_t s0 = sb + (uint32_t)(st * 4) * 8192;
        cpa16(s0 + aD0 * 4,          Ah + aS0 + ao);
        cpa16(s0 + aD1 * 4,          Ah + aS1 + ao);
        cpa16(s0 + 8192  + aD0 * 4,  Al + aS0 + ao);
        cpa16(s0 + 8192  + aD1 * 4,  Al + aS1 + ao);
        cpa16(s0 + 16384 + bD0 * 4,  Bh + bS0 + bo);
        cpa16(s0 + 16384 + bD1 * 4,  Bh + bS1 + bo);
        cpa16(s0 + 24576 + bD0 * 4,  Bl + bS0 + bo);
        cpa16(s0 + 24576 + bD1 * 4,  Bl + bS1 + bo);
        asm volatile("cp.async.commit_group;" ::: "memory");
    };

    #pragma unroll
    for (int i = 0; i < 4; i++)
        #pragma unroll
        for (int j = 0; j < 4; j++)
            #pragma unroll
            for (int r = 0; r < 4; r++) acc[i][j][r] = 0.f;

    const int nc = K >> 5;
    issue(0, 0);

    for (int c = 0; c < nc; c++) {
        const int s = c & 1;
        if (c + 1 < nc) {
            issue(c + 1, s ^ 1);
            asm volatile("cp.async.wait_group 1;" ::: "memory");
        } else {
            asm volatile("cp.async.wait_group 0;" ::: "memory");
        }
        __syncthreads();

        #pragma unroll
        for (int kt = 0; kt < 2; kt++) {
            uint4 a_h[4], a_l[4];
            #pragma unroll
            for (int i = 0; i < 4; i++) {
                int off = ((cx.wm * 4 + i) * 2 + kt) * 128 + lane * 4;
                a_h[i] = *(const uint4*)&sm[s][0][off];
                a_l[i] = *(const uint4*)&sm[s][1][off];
            }
            #pragma unroll
            for (int jp = 0; jp < 2; jp++) {
                uint2 b_h[2], b_l[2];
                #pragma unroll
                for (int jj = 0; jj < 2; jj++) {
                    int off = ((cx.wn * 4 + jp * 2 + jj) * 2 + kt) * 64 + lane * 2;
                    b_h[jj] = *(const uint2*)&sm[s][2][off];
                    b_l[jj] = *(const uint2*)&sm[s][3][off];
                }
                #pragma unroll
                for (int jj = 0; jj < 2; jj++)
                    #pragma unroll
                    for (int i = 0; i < 4; i++)
                        mma16(acc[i][jp*2+jj], a_h[i], b_h[jj]);
                #pragma unroll
                for (int jj = 0; jj < 2; jj++)
                    #pragma unroll
                    for (int i = 0; i < 4; i++)
                        mma16(acc[i][jp*2+jj], a_h[i], b_l[jj]);
                #pragma unroll
                for (int jj = 0; jj < 2; jj++)
                    #pragma unroll
                    for (int i = 0; i < 4; i++)
                        mma16(acc[i][jp*2+jj], a_l[i], b_h[jj]);
            }
        }
        __syncthreads();
    }
}

// Generic GEMM: fp32 C output
__global__ void __launch_bounds__(256, 2) gemm_fr_kernel(
    const unsigned* __restrict__ Ah, const unsigned* __restrict__ Al,
    const unsigned* __restrict__ Bh, const unsigned* __restrict__ Bl,
    float* __restrict__ C, int N, int K)
{
    __shared__ unsigned sm[2][4][2048];
    float acc[4][4][4];
    GemmCtx cx;
    gemm_main(Ah, Al, Bh, Bl, K, sm, acc, cx);

    const int g = cx.lane >> 2, q = cx.lane & 3;
    const int m0 = blockIdx.y * 128, n0 = blockIdx.x * 128;
    #pragma unroll
    for (int i = 0; i < 4; i++) {
        const int row = m0 + cx.wm * 64 + i * 16 + g;
        #pragma unroll
        for (int j = 0; j < 4; j++) {
            const int colb = n0 + cx.wn * 32 + j * 8;
            if (colb < N) {
                const int col = colb + 2 * q;
                *(float2*)&C[(size_t)row * N + col] =
                    make_float2(acc[i][j][0], acc[i][j][1]);
                *(float2*)&C[(size_t)(row + 8) * N + col] =
                    make_float2(acc[i][j][2], acc[i][j][3]);
            }
        }
    }
}

// q_b GEMM (N=3072): nope dims -> Q fragments (pre-scaled); rope dims -> sidecar
__global__ void __launch_bounds__(256, 2) gemm_qb_kernel(
    const unsigned* __restrict__ Ah, const unsigned* __restrict__ Al,
    const unsigned* __restrict__ Bh, const unsigned* __restrict__ Bl,
    int K)
{
    __shared__ unsigned sm[2][4][2048];
    float acc[4][4][4];
    GemmCtx cx;
    gemm_main(Ah, Al, Bh, Bl, K, sm, acc, cx);

    const int g = cx.lane >> 2, q = cx.lane & 3;
    const int m0 = blockIdx.y * 128, n0 = blockIdx.x * 128;
    const float scale = rsqrtf((float)DQK);

    #pragma unroll
    for (int i = 0; i < 4; i++) {
        #pragma unroll
        for (int j = 0; j < 4; j++) {
            const int col = n0 + cx.wn * 32 + j * 8 + 2 * q;
            const int h = col / 192;
            const int d = col - h * 192;
            #pragma unroll
            for (int half = 0; half < 2; half++) {
                const int t = m0 + cx.wm * 64 + i * 16 + g + half * 8;
                const float v0 = acc[i][j][half*2]     * scale;
                const float v1 = acc[i][j][half*2 + 1] * scale;
                if (d < DN) {
                    unsigned hi, lo; split2(v0, v1, hi, lo);
                    size_t off = qfrag_off(h, t, d);
                    g_Qh[off] = hi; g_Ql[off] = lo;
                } else {
                    *(float2*)&g_qrope[((size_t)t * NH + h) * DR + (d - DN)] =
                        make_float2(v0, v1);
                }
            }
        }
    }
}

// ---------------------------------------------------------------------------
__global__ void __launch_bounds__(256) rmsnormA_kernel(
    const float* __restrict__ x, const float* __restrict__ w,
    unsigned* __restrict__ Ph, unsigned* __restrict__ Pl, int ld, int n)
{
    const int row = blockIdx.x;
    const float* xr = x + (size_t)row * ld;
    float s = 0.f;
    for (int i = threadIdx.x; i < n; i += 256) { float v = xr[i]; s += v * v; }
    __shared__ float red[8];
    #pragma unroll
    for (int o = 16; o; o >>= 1) s += __shfl_xor_sync(0xffffffffu, s, o);
    if ((threadIdx.x & 31) == 0) red[threadIdx.x >> 5] = s;
    __syncthreads();
    if (threadIdx.x < 32) {
        float v = (threadIdx.x < 8) ? red[threadIdx.x] : 0.f;
        #pragma unroll
        for (int o = 4; o; o >>= 1) v += __shfl_xor_sync(0xffffffffu, v, o);
        if (threadIdx.x == 0) red[0] = v;
    }
    __syncthreads();
    const float r = rsqrtf(red[0] / (float)n + EPS);
    for (int dp = threadIdx.x; dp < (n >> 1); dp += 256) {
        int d = dp * 2;
        float v0 = w[d] * xr[d] * r, v1 = w[d + 1] * xr[d + 1] * r;
        unsigned hi, lo; split2(v0, v1, hi, lo);
        size_t off = ((size_t)(row >> 4) * (n >> 4) + (d >> 4)) * 128
                   + ((row & 7) * 4 + ((d & 7) >> 1)) * 4
                   + ((d >> 3) & 1) * 2 + ((row >> 3) & 1);
        Ph[off] = hi; Pl[off] = lo;
    }
}

// ---------------------------------------------------------------------------
// Assemble: Q-rope (from sidecar) + K (full) + V. Grid (S_LEN/2, NH).
// ---------------------------------------------------------------------------
__global__ void __launch_bounds__(256) assemble_kernel(
    const void* __restrict__ pos_ids)
{
    const int b = blockIdx.x, t0 = 2 * b, tid = threadIdx.x;
    const int h = blockIdx.y;
    __shared__ float cs[2][DR], sn[2][DR], kr[2][DR];
    __shared__ float posv[2];

    if (tid < 2) {
        const int* p32 = (const int*)pos_ids;
        int t = t0 + tid;
        long long pv = (p32[1] == 0) ? ((const long long*)pos_ids)[t]
                                     : (long long)p32[t];
        posv[tid] = (float)pv;
    }
    __syncthreads();
    if (tid < 128) {
        int tok = tid >> 6, i = tid & 63, j = i & 31;
        double e = -((double)(2 * j) / 64.0) * 13.287712379549449;
        float ang = posv[tok] * (float)exp2(e);
        cs[tok][i] = cosf(ang); sn[tok][i] = sinf(ang);
    }
    __syncthreads();
    if (tid < 128) {
        int tok = tid >> 6, i = tid & 63;
        const float* kx = g_kva + (size_t)(t0 + tok) * (KVR + DR) + KVR;
        kr[tok][i] = (i < 32) ? kx[i] * cs[tok][i] - kx[i + 32] * sn[tok][i]
                              : kx[i] * cs[tok][i] + kx[i - 32] * sn[tok][i];
    }
    __syncthreads();

    if (tid < 64) {                                   // Q-rope from sidecar
        int tok = tid >> 5, i2 = (tid & 31) * 2;      // even pair base 0..62
        int t = t0 + tok;
        const float* qr = g_qrope + ((size_t)t * NH + h) * DR;
        float v0, v1;
        if (i2 < 32) {
            v0 = qr[i2]     * cs[tok][i2]     - qr[i2 + 32] * sn[tok][i2];
            v1 = qr[i2 + 1] * cs[tok][i2 + 1] - qr[i2 + 33] * sn[tok][i2 + 1];
        } else {
            v0 = qr[i2]     * cs[tok][i2]     + qr[i2 - 32] * sn[tok][i2];
            v1 = qr[i2 + 1] * cs[tok][i2 + 1] + qr[i2 - 31] * sn[tok][i2 + 1];
        }
        unsigned hi, lo; split2(v0, v1, hi, lo);
        size_t off = qfrag_off(h, t, DN + i2);
        g_Qh[off] = hi; g_Ql[off] = lo;
    }
    if (tid >= 64 && tid < 256) {                     // K (192 threads)
        int w = tid - 64;
        int tok = w / 96, pp = w % 96, d = 2 * pp;
        int t = t0 + tok;
        const float* kvrow = g_kvb + (size_t)t * (NH*(DN+DV)) + h * (DN+DV);
        float v0, v1;
        if (d < DN) { v0 = kvrow[d]; v1 = kvrow[d + 1]; }
        else        { v0 = kr[tok][d - DN]; v1 = kr[tok][d - DN + 1]; }
        unsigned hi, lo; split2(v0, v1, hi, lo);
        int nt = t >> 3, n = t & 7;
        size_t off = ((size_t)(h * 256 + nt) * 12 + (d >> 4)) * 64
                   + (n * 4 + ((d & 7) >> 1)) * 2 + ((d >> 3) & 1);
        g_Kh[off] = hi; g_Kl[off] = lo;
    }
    if (tid < 128) {                                  // V (pairs across tokens)
        int d = tid;
        float v0 = g_kvb[(size_t)t0     * (NH*(DN+DV)) + h*(DN+DV) + DN + d];
        float v1 = g_kvb[(size_t)(t0+1) * (NH*(DN+DV)) + h*(DN+DV) + DN + d];
        unsigned hi, lo; split2(v0, v1, hi, lo);
        size_t off = ((size_t)(h * 128 + (t0 >> 4)) * 16 + (d >> 3)) * 64
                   + ((d & 7) * 4 + ((t0 & 7) >> 1)) * 2 + ((t0 >> 3) & 1);
        g_Vh[off] = hi; g_Vl[off] = lo;
    }
}

// ---------------------------------------------------------------------------
// Flash attention (R8 proven 256-CTA heavy-first version)
// ---------------------------------------------------------------------------
constexpr int FL_STAGE = 20480;
constexpr size_t FLASH_SMEM_BYTES = (12288 + 2 * FL_STAGE) * 4;

__global__ void __launch_bounds__(256) flash_kernel()
{
    const int bx = blockIdx.x;
    const int qt = 15 - (bx >> 4);
    const int h  = bx & 15;
    const int q0 = qt * 128;
    const int tid = threadIdx.x, wid = tid >> 5, lane = tid & 31;
    const int g = lane >> 2, q = lane & 3;

    extern __shared__ unsigned smu[];
    unsigned* QL = smu;
    const uint32_t sb = (uint32_t)__cvta_generic_to_shared(smu);

    uint4 qh[12];
    {
        const size_t qbase = (size_t)(h * 128 + qt * 8 + wid) * 12 * 128;
        #pragma unroll
        for (int kt = 0; kt < 12; kt++)
            qh[kt] = *(const uint4*)&g_Qh[qbase + kt * 128 + lane * 4];
        const uint4* gl = (const uint4*)(g_Ql + (size_t)(h * 128 + qt * 8) * 1536);
        uint4* dl = (uint4*)QL;
        #pragma unroll
        for (int j = 0; j < 12; j++) dl[j * 256 + tid] = gl[j * 256 + tid];
    }

    const int niter = 2 * (qt + 1);
    const int wrow0 = q0 + wid * 16;

    auto issue = [&](int it, int st) {
        const uint4* gkh = (const uint4*)(g_Kh + (size_t)(h * 256 + it * 8) * 768);
        const uint4* gkl = (const uint4*)(g_Kl + (size_t)(h * 256 + it * 8) * 768);
        const uint4* gvh = (const uint4*)(g_Vh + (size_t)(h * 128 + it * 4) * 1024);
        const uint4* gvl = (const uint4*)(g_Vl + (size_t)(h * 128 + it * 4) * 1024);
        const uint32_t s0 = sb + (12288u + (uint32_t)st * FL_STAGE) * 4;
        #pragma unroll
        for (int j = 0; j < 6; j++) {
            cpa16(s0 +         (j * 256 + tid) * 16, gkh + j * 256 + tid);
            cpa16(s0 + 24576 + (j * 256 + tid) * 16, gkl + j * 256 + tid);
        }
        #pragma unroll
        for (int j = 0; j < 4; j++) {
            cpa16(s0 + 49152 + (j * 256 + tid) * 16, gvh + j * 256 + tid);
            cpa16(s0 + 65536 + (j * 256 + tid) * 16, gvl + j * 256 + tid);
        }
        asm volatile("cp.async.commit_group;" ::: "memory");
    };

    float O[16][4];
    #pragma unroll
    for (int nt = 0; nt < 16; nt++)
        #pragma unroll
        for (int r = 0; r < 4; r++) O[nt][r] = 0.f;
    float m0 = -1e30f, m1 = -1e30f, l0 = 0.f, l1 = 0.f;

    issue(0, 0);

    for (int it = 0; it < niter; it++) {
        const int s = it & 1;
        const int k0 = it * 64;
        if (it + 1 < niter) {
            issue(it + 1, s ^ 1);
            asm volatile("cp.async.wait_group 1;" ::: "memory");
        } else {
            asm volatile("cp.async.wait_group 0;" ::: "memory");
        }
        __syncthreads();

        unsigned* KHs = smu + 12288 + s * FL_STAGE;
        unsigned* KLs = KHs + 6144;
        unsigned* VHs = KHs + 12288;
        unsigned* VLs = KHs + 16384;

        if (k0 <= wrow0 + 15) {
            float S[8][4];
            #pragma unroll
            for (int nt = 0; nt < 8; nt++)
                #pragma unroll
                for (int r = 0; r < 4; r++) S[nt][r] = 0.f;

            #pragma unroll
            for (int kt = 0; kt < 12; kt++) {
                uint4 qhv = qh[kt];
                uint4 qlv = *(const uint4*)&QL[wid * 1536 + kt * 128 + lane * 4];
                #pragma unroll
                for (int nt = 0; nt < 8; nt++) {
                    uint2 kh = *(const uint2*)&KHs[(nt * 12 + kt) * 64 + lane * 2];
                    uint2 kl = *(const uint2*)&KLs[(nt * 12 + kt) * 64 + lane * 2];
                    mma16(S[nt], qhv, kh);
                    mma16(S[nt], qhv, kl);
                    mma16(S[nt], qlv, kh);
                }
            }

            if (k0 + 63 > wrow0) {
                const int row0 = wrow0 + g, row1 = row0 + 8;
                #pragma unroll
                for (int nt = 0; nt < 8; nt++) {
                    int col = k0 + nt * 8 + 2 * q;
                    if (col     > row0) S[nt][0] = -1e30f;
                    if (col + 1 > row0) S[nt][1] = -1e30f;
                    if (col     > row1) S[nt][2] = -1e30f;
                    if (col + 1 > row1) S[nt][3] = -1e30f;
                }
            }

            float rm0 = -1e30f, rm1 = -1e30f;
            #pragma unroll
            for (int nt = 0; nt < 8; nt++) {
                rm0 = fmaxf(rm0, fmaxf(S[nt][0], S[nt][1]));
                rm1 = fmaxf(rm1, fmaxf(S[nt][2], S[nt][3]));
            }
            rm0 = fmaxf(rm0, __shfl_xor_sync(0xffffffffu, rm0, 1));
            rm0 = fmaxf(rm0, __shfl_xor_sync(0xffffffffu, rm0, 2));
            rm1 = fmaxf(rm1, __shfl_xor_sync(0xffffffffu, rm1, 1));
            rm1 = fmaxf(rm1, __shfl_xor_sync(0xffffffffu, rm1, 2));

            float mn0 = fmaxf(m0, rm0), mn1 = fmaxf(m1, rm1);
            float a0 = __expf(m0 - mn0), a1 = __expf(m1 - mn1);

            unsigned PH[8], PL[8], P8H[8], P8L[8];
            float s0 = 0.f, s1 = 0.f;
            #pragma unroll
            for (int nt = 0; nt < 8; nt++) {
                float p00 = __expf(S[nt][0] - mn0);
                float p01 = __expf(S[nt][1] - mn0);
                float p10 = __expf(S[nt][2] - mn1);
                float p11 = __expf(S[nt][3] - mn1);
                s0 += p00 + p01; s1 += p10 + p11;
                split2(p00, p01, PH[nt], PL[nt]);
                split2(p10, p11, P8H[nt], P8L[nt]);
            }
            s0 += __shfl_xor_sync(0xffffffffu, s0, 1);
            s0 += __shfl_xor_sync(0xffffffffu, s0, 2);
            s1 += __shfl_xor_sync(0xffffffffu, s1, 1);
            s1 += __shfl_xor_sync(0xffffffffu, s1, 2);

            l0 = l0 * a0 + s0; l1 = l1 * a1 + s1;
            m0 = mn0; m1 = mn1;

            #pragma unroll
            for (int nt = 0; nt < 16; nt++) {
                O[nt][0] *= a0; O[nt][1] *= a0;
                O[nt][2] *= a1; O[nt][3] *= a1;
            }

            #pragma unroll
            for (int kt2 = 0; kt2 < 4; kt2++) {
                uint4 ah = make_uint4(PH[2*kt2], P8H[2*kt2], PH[2*kt2+1], P8H[2*kt2+1]);
                uint4 al = make_uint4(PL[2*kt2], P8L[2*kt2], PL[2*kt2+1], P8L[2*kt2+1]);
                #pragma unroll
                for (int nt = 0; nt < 16; nt++) {
                    uint2 vh = *(const uint2*)&VHs[(kt2 * 16 + nt) * 64 + lane * 2];
                    uint2 vl = *(const uint2*)&VLs[(kt2 * 16 + nt) * 64 + lane * 2];
                    mma16(O[nt], ah, vh);
                    mma16(O[nt], ah, vl);
                    mma16(O[nt], al, vh);
                }
            }
        }
        __syncthreads();
    }

    const float inv0 = __fdividef(1.f, l0), inv1 = __fdividef(1.f, l1);
    const int row0 = wrow0 + g;
    const size_t baseRow = (size_t)(row0 >> 4) * 128;
    #pragma unroll
    for (int nt = 0; nt < 16; nt++) {
        const int ktv = h * 8 + (nt >> 1);
        const size_t off = (baseRow + ktv) * 128 + lane * 4 + (nt & 1) * 2;
        unsigned hi, lo;
        split2(O[nt][0] * inv0, O[nt][1] * inv0, hi, lo);
        g_AatH[off] = hi; g_AatL[off] = lo;
        split2(O[nt][2] * inv1, O[nt][3] * inv1, hi, lo);
        g_AatH[off + 1] = hi; g_AatL[off + 1] = lo;
    }
}

// ---------------------------------------------------------------------------
extern "C" void kernel_launch(void* const* d_in, const int* in_sizes, int n_in,
                              void* d_out, int out_size)
{
    const float* hs       = (const float*)d_in[0];
    const void*  pos_ids  = d_in[1];
    const float* q_a_w    = (const float*)d_in[2];
    const float* q_a_ln_w = (const float*)d_in[3];
    const float* q_b_w    = (const float*)d_in[4];
    const float* kv_a_w   = (const float*)d_in[5];
    const float* kv_a_ln_w= (const float*)d_in[6];
    const float* kv_b_w   = (const float*)d_in[7];
    const float* o_w      = (const float*)d_in[8];
    float*       out      = (float*)d_out;

    float *p_qa, *p_kva, *p_kvb;
    cudaGetSymbolAddress((void**)&p_qa,  g_qa);
    cudaGetSymbolAddress((void**)&p_kva, g_kva);
    cudaGetSymbolAddress((void**)&p_kvb, g_kvb);
    unsigned *AhsH,*AhsL,*AqaH,*AqaL,*AkvH,*AkvL,*AatH,*AatL;
    unsigned *BqaH,*BqaL,*BqbH,*BqbL,*BkaH,*BkaL,*BkbH,*BkbL,*BowH,*BowL;
    cudaGetSymbolAddress((void**)&AhsH, g_AhsH); cudaGetSymbolAddress((void**)&AhsL, g_AhsL);
    cudaGetSymbolAddress((void**)&AqaH, g_AqaH); cudaGetSymbolAddress((void**)&AqaL, g_AqaL);
    cudaGetSymbolAddress((void**)&AkvH, g_AkvH); cudaGetSymbolAddress((void**)&AkvL, g_AkvL);
    cudaGetSymbolAddress((void**)&AatH, g_AatH); cudaGetSymbolAddress((void**)&AatL, g_AatL);
    cudaGetSymbolAddress((void**)&BqaH, g_BqaH); cudaGetSymbolAddress((void**)&BqaL, g_BqaL);
    cudaGetSymbolAddress((void**)&BqbH, g_BqbH); cudaGetSymbolAddress((void**)&BqbL, g_BqbL);
    cudaGetSymbolAddress((void**)&BkaH, g_BkaH); cudaGetSymbolAddress((void**)&BkaL, g_BkaL);
    cudaGetSymbolAddress((void**)&BkbH, g_BkbH); cudaGetSymbolAddress((void**)&BkbL, g_BkbL);
    cudaGetSymbolAddress((void**)&BowH, g_BowH); cudaGetSymbolAddress((void**)&BowL, g_BowL);

    cudaFuncSetAttribute(flash_kernel,
                         cudaFuncAttributeMaxDynamicSharedMemorySize,
                         (int)FLASH_SMEM_BYTES);

    static cudaStream_t sA = nullptr, sB = nullptr;
    static cudaEvent_t evRoot, evA, evW1, evW2, evKV;
    if (!sA) {
        cudaStreamCreateWithFlags(&sA, cudaStreamNonBlocking);
        cudaStreamCreateWithFlags(&sB, cudaStreamNonBlocking);
        cudaEventCreateWithFlags(&evRoot, cudaEventDisableTiming);
        cudaEventCreateWithFlags(&evA, cudaEventDisableTiming);
        cudaEventCreateWithFlags(&evW1, cudaEventDisableTiming);
        cudaEventCreateWithFlags(&evW2, cudaEventDisableTiming);
        cudaEventCreateWithFlags(&evKV, cudaEventDisableTiming);
    }

    // fork
    cudaEventRecord(evRoot, 0);
    cudaStreamWaitEvent(sA, evRoot, 0);
    cudaStreamWaitEvent(sB, evRoot, 0);

    // main stream: q chain (R8 proven ordering)
    convB_kernel<<<6144, 256>>>(q_a_w, BqaH, BqaL, QR, HID);
    convA_kernel<<<8192, 256>>>(hs, AhsH, AhsL, HID);
    cudaEventRecord(evA, 0);
    gemm_fr_kernel<<<dim3(12, 16), 256>>>(AhsH, AhsL, BqaH, BqaL, p_qa, QR, HID);
    rmsnormA_kernel<<<S_LEN, 256>>>(p_qa, q_a_ln_w, AqaH, AqaL, QR, QR);

    // sA: kv chain (R8: fp32 g_kvb)
    convB_kernel<<<2560, 256, 0, sA>>>(kv_a_w, BkaH, BkaL, KVR + DR, HID);
    convB_kernel<<<4096, 256, 0, sA>>>(kv_b_w, BkbH, BkbL, NH * (DN + DV), KVR);
    cudaStreamWaitEvent(sA, evA, 0);
    gemm_fr_kernel<<<dim3(5, 16), 256, 0, sA>>>(AhsH, AhsL, BkaH, BkaL, p_kva,
                                                KVR + DR, HID);
    rmsnormA_kernel<<<S_LEN, 256, 0, sA>>>(p_kva, kv_a_ln_w, AkvH, AkvL,
                                           KVR + DR, KVR);
    gemm_fr_kernel<<<dim3(32, 16), 256, 0, sA>>>(AkvH, AkvL, BkbH, BkbL, p_kvb,
                                                 NH * (DN + DV), KVR);
    cudaEventRecord(evKV, sA);

    // sB: remaining weight conversions
    convB_kernel<<<9216, 256, 0, sB>>>(q_b_w, BqbH, BqbL, NH * DQK, QR);
    cudaEventRecord(evW1, sB);
    convB_kernel<<<8192, 256, 0, sB>>>(o_w, BowH, BowL, HID, HID);
    cudaEventRecord(evW2, sB);

    // join and finish on main stream
    cudaStreamWaitEvent(0, evW1, 0);
    gemm_qb_kernel<<<dim3(24, 16), 256>>>(AqaH, AqaL, BqbH, BqbL, QR);
    cudaStreamWaitEvent(0, evKV, 0);
    assemble_kernel<<<dim3(S_LEN / 2, NH), 256>>>(pos_ids);
    flash_kernel<<<256, 256, FLASH_SMEM_BYTES>>>();
    cudaStreamWaitEvent(0, evW2, 0);
    gemm_fr_kernel<<<dim3(16, 16), 256>>>(AatH, AatL, BowH, BowL, out, HID, HID);
}

// round 16
// speedup vs baseline: 1.0763x; 1.0557x over previous
#include <cuda_runtime.h>
#include <cuda_fp16.h>
#include <cstdint>

constexpr int S_LEN = 2048, HID = 2048, NH = 16, QR = 1536, KVR = 512;
constexpr int DN = 128, DR = 64, DQK = 192, DV = 128;
constexpr float EPS = 1e-6f;

__device__ float g_qa [S_LEN * QR];
__device__ float g_q  [S_LEN * NH * DQK];
__device__ float g_kva[S_LEN * (KVR + DR)];
__device__ float g_kvb[S_LEN * NH * (DN + DV)];

__device__ unsigned g_Qh[NH * (S_LEN/16) * 12 * 128];
__device__ unsigned g_Ql[NH * (S_LEN/16) * 12 * 128];
__device__ unsigned g_Kh[NH * (S_LEN/8)  * 12 * 64];
__device__ unsigned g_Kl[NH * (S_LEN/8)  * 12 * 64];
__device__ unsigned g_Vh[NH * (S_LEN/16) * 16 * 64];
__device__ unsigned g_Vl[NH * (S_LEN/16) * 16 * 64];

__device__ unsigned g_AhsH [2097152], g_AhsL [2097152];
__device__ unsigned g_AqaH [1572864], g_AqaL [1572864];
__device__ unsigned g_AkvH [524288],  g_AkvL [524288];
__device__ unsigned g_AatH [2097152], g_AatL [2097152];
__device__ unsigned g_BqaH [1572864], g_BqaL [1572864];
__device__ unsigned g_BqbH [2359296], g_BqbL [2359296];
__device__ unsigned g_BkaH [655360],  g_BkaL [655360];
__device__ unsigned g_BkbH [1048576], g_BkbL [1048576];
__device__ unsigned g_BowH [2097152], g_BowL [2097152];

__device__ __forceinline__ void split2(float x0, float x1,
                                       unsigned& hi, unsigned& lo) {
    __half h0 = __float2half_rn(x0), h1 = __float2half_rn(x1);
    __half l0 = __float2half_rn(x0 - __half2float(h0));
    __half l1 = __float2half_rn(x1 - __half2float(h1));
    hi = (unsigned)__half_as_ushort(h0) | ((unsigned)__half_as_ushort(h1) << 16);
    lo = (unsigned)__half_as_ushort(l0) | ((unsigned)__half_as_ushort(l1) << 16);
}

__device__ __forceinline__ void mma16(float* c, const uint4& a, const uint2& b) {
    asm volatile(
        "mma.sync.aligned.m16n8k16.row.col.f32.f16.f16.f32 "
        "{%0,%1,%2,%3}, {%4,%5,%6,%7}, {%8,%9}, {%0,%1,%2,%3};"
        : "+f"(c[0]), "+f"(c[1]), "+f"(c[2]), "+f"(c[3])
        : "r"(a.x), "r"(a.y), "r"(a.z), "r"(a.w), "r"(b.x), "r"(b.y));
}

__device__ __forceinline__ void cpa16(uint32_t dst, const void* src) {
    asm volatile("cp.async.cg.shared.global [%0], [%1], 16;"
                 :: "r"(dst), "l"(src) : "memory");
}

// ---------------------------------------------------------------------------
__global__ void __launch_bounds__(256) convA_kernel(
    const float* __restrict__ X, unsigned* __restrict__ Ph,
    unsigned* __restrict__ Pl, int K)
{
    size_t id = (size_t)blockIdx.x * 256 + threadIdx.x;
    int m = (int)(id / (K >> 1));
    int d = (int)(id % (K >> 1)) * 2;
    float2 v = *(const float2*)&X[(size_t)m * K + d];
    unsigned hi, lo; split2(v.x, v.y, hi, lo);
    size_t off = ((size_t)(m >> 4) * (K >> 4) + (d >> 4)) * 128
               + ((m & 7) * 4 + ((d & 7) >> 1)) * 4
               + ((d >> 3) & 1) * 2 + ((m >> 3) & 1);
    Ph[off] = hi; Pl[off] = lo;
}

__global__ void __launch_bounds__(256) convB_kernel(
    const float* __restrict__ W, unsigned* __restrict__ Ph,
    unsigned* __restrict__ Pl, int N, int K)
{
    size_t id = (size_t)blockIdx.x * 256 + threadIdx.x;
    int n = (int)(id / (K >> 1));
    int d = (int)(id % (K >> 1)) * 2;
    float v0 = 0.f, v1 = 0.f;
    if (n < N) { float2 v = *(const float2*)&W[(size_t)n * K + d]; v0 = v.x; v1 = v.y; }
    unsigned hi, lo; split2(v0, v1, hi, lo);
    size_t off = ((size_t)(n >> 3) * (K >> 4) + (d >> 4)) * 64
               + ((n & 7) * 4 + ((d & 7) >> 1)) * 2 + ((d >> 3) & 1);
    Ph[off] = hi; Pl[off] = lo;
}

// ---------------------------------------------------------------------------
// GEMM mainloop. THREE=true: fp16x3 (hi*hi + hi*lo + lo*hi).
// THREE=false: fp16x2 (hi*hi + hi*lo), skips the A-lo plane entirely.
// ---------------------------------------------------------------------------
template<bool THREE>
__global__ void __launch_bounds__(256, 2) gemm_t_kernel(
    const unsigned* __restrict__ Ah, const unsigned* __restrict__ Al,
    const unsigned* __restrict__ Bh, const unsigned* __restrict__ Bl,
    float* __restrict__ C, int N, int K)
{
    __shared__ unsigned sm[2][4][2048];

    const int tid = threadIdx.x, lane = tid & 31, warp = tid >> 5;
    const int wm = warp >> 2, wn = warp & 3;
    const int m0t = blockIdx.y * 8, n0t = blockIdx.x * 16;
    const int KT = K >> 4;

    const int f0 = tid, f1 = tid + 256;
    const int aM0 = f0 >> 6, aK0 = (f0 & 63) >> 5, aW0 = f0 & 31;
    const int aM1 = f1 >> 6, aK1 = (f1 & 63) >> 5, aW1 = f1 & 31;
    const size_t aS0 = ((size_t)(m0t + aM0) * KT + aK0) * 128 + aW0 * 4;
    const size_t aS1 = ((size_t)(m0t + aM1) * KT + aK1) * 128 + aW1 * 4;
    const int aD0 = (aM0 * 2 + aK0) * 128 + aW0 * 4;
    const int aD1 = (aM1 * 2 + aK1) * 128 + aW1 * 4;
    const int bN0 = f0 >> 5, bK0 = (f0 & 31) >> 4, bW0 = f0 & 15;
    const int bN1 = f1 >> 5, bK1 = (f1 & 31) >> 4, bW1 = f1 & 15;
    const size_t bS0 = ((size_t)(n0t + bN0) * KT + bK0) * 64 + bW0 * 4;
    const size_t bS1 = ((size_t)(n0t + bN1) * KT + bK1) * 64 + bW1 * 4;
    const int bD0 = (bN0 * 2 + bK0) * 64 + bW0 * 4;
    const int bD1 = (bN1 * 2 + bK1) * 64 + bW1 * 4;

    const uint32_t sb = (uint32_t)__cvta_generic_to_shared(&sm[0][0][0]);
    auto issue = [&](int c, int st) {
        const size_t ao = (size_t)c * 256, bo = (size_t)c * 128;
        const uint32_t s0 = sb + (uint32_t)(st * 4) * 8192;
        cpa16(s0 + aD0 * 4,          Ah + aS0 + ao);
        cpa16(s0 + aD1 * 4,          Ah + aS1 + ao);
        if (THREE) {
            cpa16(s0 + 8192  + aD0 * 4,  Al + aS0 + ao);
            cpa16(s0 + 8192  + aD1 * 4,  Al + aS1 + ao);
        }
        cpa16(s0 + 16384 + bD0 * 4,  Bh + bS0 + bo);
        cpa16(s0 + 16384 + bD1 * 4,  Bh + bS1 + bo);
        cpa16(s0 + 24576 + bD0 * 4,  Bl + bS0 + bo);
        cpa16(s0 + 24576 + bD1 * 4,  Bl + bS1 + bo);
        asm volatile("cp.async.commit_group;" ::: "memory");
    };

    float acc[4][4][4];
    #pragma unroll
    for (int i = 0; i < 4; i++)
        #pragma unroll
        for (int j = 0; j < 4; j++)
            #pragma unroll
            for (int r = 0; r < 4; r++) acc[i][j][r] = 0.f;

    const int nc = K >> 5;
    issue(0, 0);

    for (int c = 0; c < nc; c++) {
        const int s = c & 1;
        if (c + 1 < nc) {
            issue(c + 1, s ^ 1);
            asm volatile("cp.async.wait_group 1;" ::: "memory");
        } else {
            asm volatile("cp.async.wait_group 0;" ::: "memory");
        }
        __syncthreads();

        #pragma unroll
        for (int kt = 0; kt < 2; kt++) {
            uint4 a_h[4], a_l[4];
            #pragma unroll
            for (int i = 0; i < 4; i++) {
                int off = ((wm * 4 + i) * 2 + kt) * 128 + lane * 4;
                a_h[i] = *(const uint4*)&sm[s][0][off];
                if (THREE) a_l[i] = *(const uint4*)&sm[s][1][off];
            }
            #pragma unroll
            for (int jp = 0; jp < 2; jp++) {
                uint2 b_h[2], b_l[2];
                #pragma unroll
                for (int jj = 0; jj < 2; jj++) {
                    int off = ((wn * 4 + jp * 2 + jj) * 2 + kt) * 64 + lane * 2;
                    b_h[jj] = *(const uint2*)&sm[s][2][off];
                    b_l[jj] = *(const uint2*)&sm[s][3][off];
                }
                #pragma unroll
                for (int jj = 0; jj < 2; jj++)
                    #pragma unroll
                    for (int i = 0; i < 4; i++)
                        mma16(acc[i][jp*2+jj], a_h[i], b_h[jj]);
                #pragma unroll
                for (int jj = 0; jj < 2; jj++)
                    #pragma unroll
                    for (int i = 0; i < 4; i++)
                        mma16(acc[i][jp*2+jj], a_h[i], b_l[jj]);
                if (THREE) {
                    #pragma unroll
                    for (int jj = 0; jj < 2; jj++)
                        #pragma unroll
                        for (int i = 0; i < 4; i++)
                            mma16(acc[i][jp*2+jj], a_l[i], b_h[jj]);
                }
            }
        }
        __syncthreads();
    }

    const int g = lane >> 2, q = lane & 3;
    const int m0 = blockIdx.y * 128, n0 = blockIdx.x * 128;
    #pragma unroll
    for (int i = 0; i < 4; i++) {
        const int row = m0 + wm * 64 + i * 16 + g;
        #pragma unroll
        for (int j = 0; j < 4; j++) {
            const int colb = n0 + wn * 32 + j * 8;
            if (colb < N) {
                const int col = colb + 2 * q;
                *(float2*)&C[(size_t)row * N + col] =
                    make_float2(acc[i][j][0], acc[i][j][1]);
                *(float2*)&C[(size_t)(row + 8) * N + col] =
                    make_float2(acc[i][j][2], acc[i][j][3]);
            }
        }
    }
}

// ---------------------------------------------------------------------------
__global__ void __launch_bounds__(256) rmsnormA_kernel(
    const float* __restrict__ x, const float* __restrict__ w,
    unsigned* __restrict__ Ph, unsigned* __restrict__ Pl, int ld, int n)
{
    const int row = blockIdx.x;
    const float* xr = x + (size_t)row * ld;
    float s = 0.f;
    for (int i = threadIdx.x; i < n; i += 256) { float v = xr[i]; s += v * v; }
    __shared__ float red[8];
    #pragma unroll
    for (int o = 16; o; o >>= 1) s += __shfl_xor_sync(0xffffffffu, s, o);
    if ((threadIdx.x & 31) == 0) red[threadIdx.x >> 5] = s;
    __syncthreads();
    if (threadIdx.x < 32) {
        float v = (threadIdx.x < 8) ? red[threadIdx.x] : 0.f;
        #pragma unroll
        for (int o = 4; o; o >>= 1) v += __shfl_xor_sync(0xffffffffu, v, o);
        if (threadIdx.x == 0) red[0] = v;
    }
    __syncthreads();
    const float r = rsqrtf(red[0] / (float)n + EPS);
    for (int dp = threadIdx.x; dp < (n >> 1); dp += 256) {
        int d = dp * 2;
        float v0 = w[d] * xr[d] * r, v1 = w[d + 1] * xr[d + 1] * r;
        unsigned hi, lo; split2(v0, v1, hi, lo);
        size_t off = ((size_t)(row >> 4) * (n >> 4) + (d >> 4)) * 128
                   + ((row & 7) * 4 + ((d & 7) >> 1)) * 4
                   + ((d >> 3) & 1) * 2 + ((row >> 3) & 1);
        Ph[off] = hi; Pl[off] = lo;
    }
}

// ---------------------------------------------------------------------------
__global__ void __launch_bounds__(256) assemble_kernel(
    const void* __restrict__ pos_ids)
{
    const int b = blockIdx.x, t0 = 2 * b, tid = threadIdx.x;
    const int h = blockIdx.y;
    __shared__ float cs[2][DR], sn[2][DR], kr[2][DR];
    __shared__ float posv[2];

    if (tid < 2) {
        const int* p32 = (const int*)pos_ids;
        int t = t0 + tid;
        long long pv = (p32[1] == 0) ? ((const long long*)pos_ids)[t]
                                     : (long long)p32[t];
        posv[tid] = (float)pv;
    }
    __syncthreads();
    if (tid < 128) {
        int tok = tid >> 6, i = tid & 63, j = i & 31;
        double e = -((double)(2 * j) / 64.0) * 13.287712379549449;
        float ang = posv[tok] * (float)exp2(e);
        cs[tok][i] = cosf(ang); sn[tok][i] = sinf(ang);
    }
    __syncthreads();
    if (tid < 128) {
        int tok = tid >> 6, i = tid & 63;
        const float* kx = g_kva + (size_t)(t0 + tok) * (KVR + DR) + KVR;
        kr[tok][i] = (i < 32) ? kx[i] * cs[tok][i] - kx[i + 32] * sn[tok][i]
                              : kx[i] * cs[tok][i] + kx[i - 32] * sn[tok][i];
    }
    __syncthreads();

    const float scale = rsqrtf((float)DQK);

    if (tid < 192) {                                  // Q
        int tok = tid / 96, pp = tid % 96, d = 2 * pp;
        int t = t0 + tok;
        const float* qrow = g_q + (size_t)t * (NH * DQK) + h * DQK;
        float v0, v1;
        if (d < DN) { v0 = qrow[d]; v1 = qrow[d + 1]; }
        else {
            int i = d - DN;
            if (i < 32) {
                v0 = qrow[d]   * cs[tok][i]   - qrow[d + 32] * sn[tok][i];
                v1 = qrow[d+1] * cs[tok][i+1] - qrow[d + 33] * sn[tok][i+1];
            } else {
                v0 = qrow[d]   * cs[tok][i]   + qrow[d - 32] * sn[tok][i];
                v1 = qrow[d+1] * cs[tok][i+1] + qrow[d - 31] * sn[tok][i+1];
            }
        }
        v0 *= scale; v1 *= scale;
        unsigned hi, lo; split2(v0, v1, hi, lo);
        int mt = t >> 4, r = t & 15;
        size_t off = ((size_t)(h * 128 + mt) * 12 + (d >> 4)) * 128
                   + ((r & 7) * 4 + ((d & 7) >> 1)) * 4
                   + (((d >> 3) & 1) * 2 + (r >> 3));
        g_Qh[off] = hi; g_Ql[off] = lo;
    }
    if (tid < 192) {                                  // K
        int tok = tid / 96, pp = tid % 96, d = 2 * pp;
        int t = t0 + tok;
        const float* kvrow = g_kvb + (size_t)t * (NH*(DN+DV)) + h * (DN+DV);
        float v0, v1;
        if (d < DN) { v0 = kvrow[d]; v1 = kvrow[d + 1]; }
        else        { v0 = kr[tok][d - DN]; v1 = kr[tok][d - DN + 1]; }
        unsigned hi, lo; split2(v0, v1, hi, lo);
        int nt = t >> 3, n = t & 7;
        size_t off = ((size_t)(h * 256 + nt) * 12 + (d >> 4)) * 64
                   + (n * 4 + ((d & 7) >> 1)) * 2 + ((d >> 3) & 1);
        g_Kh[off] = hi; g_Kl[off] = lo;
    }
    if (tid >= 64 && tid < 192) {                     // V
        int d = tid - 64;
        float v0 = g_kvb[(size_t)t0     * (NH*(DN+DV)) + h*(DN+DV) + DN + d];
        float v1 = g_kvb[(size_t)(t0+1) * (NH*(DN+DV)) + h*(DN+DV) + DN + d];
        unsigned hi, lo; split2(v0, v1, hi, lo);
        size_t off = ((size_t)(h * 128 + (t0 >> 4)) * 16 + (d >> 3)) * 64
                   + ((d & 7) * 4 + ((t0 & 7) >> 1)) * 2 + ((t0 >> 3) & 1);
        g_Vh[off] = hi; g_Vl[off] = lo;
    }
}

// ---------------------------------------------------------------------------
constexpr int FL_STAGE = 20480;
constexpr size_t FLASH_SMEM_BYTES = (12288 + 2 * FL_STAGE) * 4;

__global__ void __launch_bounds__(256) flash_kernel()
{
    const int bx = blockIdx.x;
    const int qt = 15 - (bx >> 4);
    const int h  = bx & 15;
    const int q0 = qt * 128;
    const int tid = threadIdx.x, wid = tid >> 5, lane = tid & 31;
    const int g = lane >> 2, q = lane & 3;

    extern __shared__ unsigned smu[];
    unsigned* QL = smu;
    const uint32_t sb = (uint32_t)__cvta_generic_to_shared(smu);

    uint4 qh[12];
    {
        const size_t qbase = (size_t)(h * 128 + qt * 8 + wid) * 12 * 128;
        #pragma unroll
        for (int kt = 0; kt < 12; kt++)
            qh[kt] = *(const uint4*)&g_Qh[qbase + kt * 128 + lane * 4];
        const uint4* gl = (const uint4*)(g_Ql + (size_t)(h * 128 + qt * 8) * 1536);
        uint4* dl = (uint4*)QL;
        #pragma unroll
        for (int j = 0; j < 12; j++) dl[j * 256 + tid] = gl[j * 256 + tid];
    }

    const int niter = 2 * (qt + 1);
    const int wrow0 = q0 + wid * 16;

    auto issue = [&](int it, int st) {
        const uint4* gkh = (const uint4*)(g_Kh + (size_t)(h * 256 + it * 8) * 768);
        const uint4* gkl = (const uint4*)(g_Kl + (size_t)(h * 256 + it * 8) * 768);
        const uint4* gvh = (const uint4*)(g_Vh + (size_t)(h * 128 + it * 4) * 1024);
        const uint4* gvl = (const uint4*)(g_Vl + (size_t)(h * 128 + it * 4) * 1024);
        const uint32_t s0 = sb + (12288u + (uint32_t)st * FL_STAGE) * 4;
        #pragma unroll
        for (int j = 0; j < 6; j++) {
            cpa16(s0 +         (j * 256 + tid) * 16, gkh + j * 256 + tid);
            cpa16(s0 + 24576 + (j * 256 + tid) * 16, gkl + j * 256 + tid);
        }
        #pragma unroll
        for (int j = 0; j < 4; j++) {
            cpa16(s0 + 49152 + (j * 256 + tid) * 16, gvh + j * 256 + tid);
            cpa16(s0 + 65536 + (j * 256 + tid) * 16, gvl + j * 256 + tid);
        }
        asm volatile("cp.async.commit_group;" ::: "memory");
    };

    float O[16][4];
    #pragma unroll
    for (int nt = 0; nt < 16; nt++)
        #pragma unroll
        for (int r = 0; r < 4; r++) O[nt][r] = 0.f;
    float m0 = -1e30f, m1 = -1e30f, l0 = 0.f, l1 = 0.f;

    issue(0, 0);

    for (int it = 0; it < niter; it++) {
        const int s = it & 1;
        const int k0 = it * 64;
        if (it + 1 < niter) {
            issue(it + 1, s ^ 1);
            asm volatile("cp.async.wait_group 1;" ::: "memory");
        } else {
            asm volatile("cp.async.wait_group 0;" ::: "memory");
        }
        __syncthreads();

        unsigned* KHs = smu + 12288 + s * FL_STAGE;
        unsigned* KLs = KHs + 6144;
        unsigned* VHs = KHs + 12288;
        unsigned* VLs = KHs + 16384;

        if (k0 <= wrow0 + 15) {
            float S[8][4];
            #pragma unroll
            for (int nt = 0; nt < 8; nt++)
                #pragma unroll
                for (int r = 0; r < 4; r++) S[nt][r] = 0.f;

            #pragma unroll
            for (int kt = 0; kt < 12; kt++) {
                uint4 qhv = qh[kt];
                uint4 qlv = *(const uint4*)&QL[wid * 1536 + kt * 128 + lane * 4];
                #pragma unroll
                for (int nt = 0; nt < 8; nt++) {
                    uint2 kh = *(const uint2*)&KHs[(nt * 12 + kt) * 64 + lane * 2];
                    uint2 kl = *(const uint2*)&KLs[(nt * 12 + kt) * 64 + lane * 2];
                    mma16(S[nt], qhv, kh);
                    mma16(S[nt], qhv, kl);
                    mma16(S[nt], qlv, kh);
                }
            }

            if (k0 + 63 > wrow0) {
                const int row0 = wrow0 + g, row1 = row0 + 8;
                #pragma unroll
                for (int nt = 0; nt < 8; nt++) {
                    int col = k0 + nt * 8 + 2 * q;
                    if (col     > row0) S[nt][0] = -1e30f;
                    if (col + 1 > row0) S[nt][1] = -1e30f;
                    if (col     > row1) S[nt][2] = -1e30f;
                    if (col + 1 > row1) S[nt][3] = -1e30f;
                }
            }

            float rm0 = -1e30f, rm1 = -1e30f;
            #pragma unroll
            for (int nt = 0; nt < 8; nt++) {
                rm0 = fmaxf(rm0, fmaxf(S[nt][0], S[nt][1]));
                rm1 = fmaxf(rm1, fmaxf(S[nt][2], S[nt][3]));
            }
            rm0 = fmaxf(rm0, __shfl_xor_sync(0xffffffffu, rm0, 1));
            rm0 = fmaxf(rm0, __shfl_xor_sync(0xffffffffu, rm0, 2));
            rm1 = fmaxf(rm1, __shfl_xor_sync(0xffffffffu, rm1, 1));
            rm1 = fmaxf(rm1, __shfl_xor_sync(0xffffffffu, rm1, 2));

            float mn0 = fmaxf(m0, rm0), mn1 = fmaxf(m1, rm1);
            float a0 = __expf(m0 - mn0), a1 = __expf(m1 - mn1);

            unsigned PH[8], PL[8], P8H[8], P8L[8];
            float s0 = 0.f, s1 = 0.f;
            #pragma unroll
            for (int nt = 0; nt < 8; nt++) {
                float p00 = __expf(S[nt][0] - mn0);
                float p01 = __expf(S[nt][1] - mn0);
                float p10 = __expf(S[nt][2] - mn1);
                float p11 = __expf(S[nt][3] - mn1);
                s0 += p00 + p01; s1 += p10 + p11;
                split2(p00, p01, PH[nt], PL[nt]);
                split2(p10, p11, P8H[nt], P8L[nt]);
            }
            s0 += __shfl_xor_sync(0xffffffffu, s0, 1);
            s0 += __shfl_xor_sync(0xffffffffu, s0, 2);
            s1 += __shfl_xor_sync(0xffffffffu, s1, 1);
            s1 += __shfl_xor_sync(0xffffffffu, s1, 2);

            l0 = l0 * a0 + s0; l1 = l1 * a1 + s1;
            m0 = mn0; m1 = mn1;

            #pragma unroll
            for (int nt = 0; nt < 16; nt++) {
                O[nt][0] *= a0; O[nt][1] *= a0;
                O[nt][2] *= a1; O[nt][3] *= a1;
            }

            #pragma unroll
            for (int kt2 = 0; kt2 < 4; kt2++) {
                uint4 ah = make_uint4(PH[2*kt2], P8H[2*kt2], PH[2*kt2+1], P8H[2*kt2+1]);
                uint4 al = make_uint4(PL[2*kt2], P8L[2*kt2], PL[2*kt2+1], P8L[2*kt2+1]);
                #pragma unroll
                for (int nt = 0; nt < 16; nt++) {
                    uint2 vh = *(const uint2*)&VHs[(kt2 * 16 + nt) * 64 + lane * 2];
                    uint2 vl = *(const uint2*)&VLs[(kt2 * 16 + nt) * 64 + lane * 2];
                    mma16(O[nt], ah, vh);
                    mma16(O[nt], ah, vl);
                    mma16(O[nt], al, vh);
                }
            }
        }
        __syncthreads();
    }

    const float inv0 = __fdividef(1.f, l0), inv1 = __fdividef(1.f, l1);
    const int row0 = wrow0 + g;
    const size_t baseRow = (size_t)(row0 >> 4) * 128;
    #pragma unroll
    for (int nt = 0; nt < 16; nt++) {
        const int ktv = h * 8 + (nt >> 1);
        const size_t off = (baseRow + ktv) * 128 + lane * 4 + (nt & 1) * 2;
        unsigned hi, lo;
        split2(O[nt][0] * inv0, O[nt][1] * inv0, hi, lo);
        g_AatH[off] = hi; g_AatL[off] = lo;
        split2(O[nt][2] * inv1, O[nt][3] * inv1, hi, lo);
        g_AatH[off + 1] = hi; g_AatL[off + 1] = lo;
    }
}

// ---------------------------------------------------------------------------
extern "C" void kernel_launch(void* const* d_in, const int* in_sizes, int n_in,
                              void* d_out, int out_size)
{
    const float* hs       = (const float*)d_in[0];
    const void*  pos_ids  = d_in[1];
    const float* q_a_w    = (const float*)d_in[2];
    const float* q_a_ln_w = (const float*)d_in[3];
    const float* q_b_w    = (const float*)d_in[4];
    const float* kv_a_w   = (const float*)d_in[5];
    const float* kv_a_ln_w= (const float*)d_in[6];
    const float* kv_b_w   = (const float*)d_in[7];
    const float* o_w      = (const float*)d_in[8];
    float*       out      = (float*)d_out;

    float *p_qa, *p_q, *p_kva, *p_kvb;
    cudaGetSymbolAddress((void**)&p_qa,  g_qa);
    cudaGetSymbolAddress((void**)&p_q,   g_q);
    cudaGetSymbolAddress((void**)&p_kva, g_kva);
    cudaGetSymbolAddress((void**)&p_kvb, g_kvb);
    unsigned *AhsH,*AhsL,*AqaH,*AqaL,*AkvH,*AkvL,*AatH,*AatL;
    unsigned *BqaH,*BqaL,*BqbH,*BqbL,*BkaH,*BkaL,*BkbH,*BkbL,*BowH,*BowL;
    cudaGetSymbolAddress((void**)&AhsH, g_AhsH); cudaGetSymbolAddress((void**)&AhsL, g_AhsL);
    cudaGetSymbolAddress((void**)&AqaH, g_AqaH); cudaGetSymbolAddress((void**)&AqaL, g_AqaL);
    cudaGetSymbolAddress((void**)&AkvH, g_AkvH); cudaGetSymbolAddress((void**)&AkvL, g_AkvL);
    cudaGetSymbolAddress((void**)&AatH, g_AatH); cudaGetSymbolAddress((void**)&AatL, g_AatL);
    cudaGetSymbolAddress((void**)&BqaH, g_BqaH); cudaGetSymbolAddress((void**)&BqaL, g_BqaL);
    cudaGetSymbolAddress((void**)&BqbH, g_BqbH); cudaGetSymbolAddress((void**)&BqbL, g_BqbL);
    cudaGetSymbolAddress((void**)&BkaH, g_BkaH); cudaGetSymbolAddress((void**)&BkaL, g_BkaL);
    cudaGetSymbolAddress((void**)&BkbH, g_BkbH); cudaGetSymbolAddress((void**)&BkbL, g_BkbL);
    cudaGetSymbolAddress((void**)&BowH, g_BowH); cudaGetSymbolAddress((void**)&BowL, g_BowL);

    cudaFuncSetAttribute(flash_kernel,
                         cudaFuncAttributeMaxDynamicSharedMemorySize,
                         (int)FLASH_SMEM_BYTES);

    static cudaStream_t sA = nullptr, sB = nullptr;
    static cudaEvent_t evRoot, evA, evW1, evW2, evKV;
    if (!sA) {
        cudaStreamCreateWithFlags(&sA, cudaStreamNonBlocking);
        cudaStreamCreateWithFlags(&sB, cudaStreamNonBlocking);
        cudaEventCreateWithFlags(&evRoot, cudaEventDisableTiming);
        cudaEventCreateWithFlags(&evA, cudaEventDisableTiming);
        cudaEventCreateWithFlags(&evW1, cudaEventDisableTiming);
        cudaEventCreateWithFlags(&evW2, cudaEventDisableTiming);
        cudaEventCreateWithFlags(&evKV, cudaEventDisableTiming);
    }

    // fork
    cudaEventRecord(evRoot, 0);
    cudaStreamWaitEvent(sA, evRoot, 0);
    cudaStreamWaitEvent(sB, evRoot, 0);

    // main stream: q chain (R8 proven ordering)
    convB_kernel<<<6144, 256>>>(q_a_w, BqaH, BqaL, QR, HID);
    convA_kernel<<<8192, 256>>>(hs, AhsH, AhsL, HID);
    cudaEventRecord(evA, 0);
    gemm_t_kernel<true><<<dim3(12, 16), 256>>>(AhsH, AhsL, BqaH, BqaL, p_qa, QR, HID);
    rmsnormA_kernel<<<S_LEN, 256>>>(p_qa, q_a_ln_w, AqaH, AqaL, QR, QR);

    // sA: kv chain
    convB_kernel<<<2560, 256, 0, sA>>>(kv_a_w, BkaH, BkaL, KVR + DR, HID);
    convB_kernel<<<4096, 256, 0, sA>>>(kv_b_w, BkbH, BkbL, NH * (DN + DV), KVR);
    cudaStreamWaitEvent(sA, evA, 0);
    gemm_t_kernel<true><<<dim3(5, 16), 256, 0, sA>>>(AhsH, AhsL, BkaH, BkaL, p_kva,
                                                     KVR + DR, HID);
    rmsnormA_kernel<<<S_LEN, 256, 0, sA>>>(p_kva, kv_a_ln_w, AkvH, AkvL,
                                           KVR + DR, KVR);
    gemm_t_kernel<true><<<dim3(32, 16), 256, 0, sA>>>(AkvH, AkvL, BkbH, BkbL, p_kvb,
                                                      NH * (DN + DV), KVR);
    cudaEventRecord(evKV, sA);

    // sB: remaining weight conversions
    convB_kernel<<<9216, 256, 0, sB>>>(q_b_w, BqbH, BqbL, NH * DQK, QR);
    cudaEventRecord(evW1, sB);
    convB_kernel<<<8192, 256, 0, sB>>>(o_w, BowH, BowL, HID, HID);
    cudaEventRecord(evW2, sB);

    // join and finish on main stream
    cudaStreamWaitEvent(0, evW1, 0);
    gemm_t_kernel<true><<<dim3(24, 16), 256>>>(AqaH, AqaL, BqbH, BqbL, p_q,
                                               NH * DQK, QR);
    cudaStreamWaitEvent(0, evKV, 0);
    assemble_kernel<<<dim3(S_LEN / 2, NH), 256>>>(pos_ids);
    flash_kernel<<<256, 256, FLASH_SMEM_BYTES>>>();
    cudaStreamWaitEvent(0, evW2, 0);
    // final projection: fp16x2 (A-lo dropped) — last linear op, error ~1e-4
    gemm_t_kernel<false><<<dim3(16, 16), 256>>>(AatH, AatL, BowH, BowL, out,
                                                HID, HID);
}

// round 17
// speedup vs baseline: 1.1201x; 1.0406x over previous
#include <cuda_runtime.h>
#include <cuda_fp16.h>
#include <cstdint>

constexpr int S_LEN = 2048, HID = 2048, NH = 16, QR = 1536, KVR = 512;
constexpr int DN = 128, DR = 64, DQK = 192, DV = 128;
constexpr float EPS = 1e-6f;

__device__ float g_qa [S_LEN * QR];
__device__ float g_q  [S_LEN * NH * DQK];
__device__ float g_kva[S_LEN * (KVR + DR)];
__device__ float g_kvb[S_LEN * NH * (DN + DV)];

__device__ unsigned g_Qh[NH * (S_LEN/16) * 12 * 128];
__device__ unsigned g_Kh[NH * (S_LEN/8)  * 12 * 64];
__device__ unsigned g_Kl[NH * (S_LEN/8)  * 12 * 64];
__device__ unsigned g_Vh[NH * (S_LEN/16) * 16 * 64];
__device__ unsigned g_Vl[NH * (S_LEN/16) * 16 * 64];

__device__ unsigned g_AhsH [2097152], g_AhsL [2097152];
__device__ unsigned g_AqaH [1572864], g_AqaL [1572864];
__device__ unsigned g_AkvH [524288],  g_AkvL [524288];
__device__ unsigned g_AatH [2097152], g_AatL [2097152];
__device__ unsigned g_BqaH [1572864], g_BqaL [1572864];
__device__ unsigned g_BqbH [2359296], g_BqbL [2359296];
__device__ unsigned g_BkaH [655360],  g_BkaL [655360];
__device__ unsigned g_BkbH [1048576], g_BkbL [1048576];
__device__ unsigned g_BowH [2097152], g_BowL [2097152];

__device__ __forceinline__ void split2(float x0, float x1,
                                       unsigned& hi, unsigned& lo) {
    __half h0 = __float2half_rn(x0), h1 = __float2half_rn(x1);
    __half l0 = __float2half_rn(x0 - __half2float(h0));
    __half l1 = __float2half_rn(x1 - __half2float(h1));
    hi = (unsigned)__half_as_ushort(h0) | ((unsigned)__half_as_ushort(h1) << 16);
    lo = (unsigned)__half_as_ushort(l0) | ((unsigned)__half_as_ushort(l1) << 16);
}

__device__ __forceinline__ unsigned pack2h(float x0, float x1) {
    __half2 h = __floats2half2_rn(x0, x1);
    return *(unsigned*)&h;
}

__device__ __forceinline__ void mma16(float* c, const uint4& a, const uint2& b) {
    asm volatile(
        "mma.sync.aligned.m16n8k16.row.col.f32.f16.f16.f32 "
        "{%0,%1,%2,%3}, {%4,%5,%6,%7}, {%8,%9}, {%0,%1,%2,%3};"
        : "+f"(c[0]), "+f"(c[1]), "+f"(c[2]), "+f"(c[3])
        : "r"(a.x), "r"(a.y), "r"(a.z), "r"(a.w), "r"(b.x), "r"(b.y));
}

__device__ __forceinline__ void cpa16(uint32_t dst, const void* src) {
    asm volatile("cp.async.cg.shared.global [%0], [%1], 16;"
                 :: "r"(dst), "l"(src) : "memory");
}

// ---------------------------------------------------------------------------
__global__ void __launch_bounds__(256) convA_kernel(
    const float* __restrict__ X, unsigned* __restrict__ Ph,
    unsigned* __restrict__ Pl, int K)
{
    size_t id = (size_t)blockIdx.x * 256 + threadIdx.x;
    int m = (int)(id / (K >> 1));
    int d = (int)(id % (K >> 1)) * 2;
    float2 v = *(const float2*)&X[(size_t)m * K + d];
    unsigned hi, lo; split2(v.x, v.y, hi, lo);
    size_t off = ((size_t)(m >> 4) * (K >> 4) + (d >> 4)) * 128
               + ((m & 7) * 4 + ((d & 7) >> 1)) * 4
               + ((d >> 3) & 1) * 2 + ((m >> 3) & 1);
    Ph[off] = hi; Pl[off] = lo;
}

__global__ void __launch_bounds__(256) convB_kernel(
    const float* __restrict__ W, unsigned* __restrict__ Ph,
    unsigned* __restrict__ Pl, int N, int K)
{
    size_t id = (size_t)blockIdx.x * 256 + threadIdx.x;
    int n = (int)(id / (K >> 1));
    int d = (int)(id % (K >> 1)) * 2;
    float v0 = 0.f, v1 = 0.f;
    if (n < N) { float2 v = *(const float2*)&W[(size_t)n * K + d]; v0 = v.x; v1 = v.y; }
    unsigned hi, lo; split2(v0, v1, hi, lo);
    size_t off = ((size_t)(n >> 3) * (K >> 4) + (d >> 4)) * 64
               + ((n & 7) * 4 + ((d & 7) >> 1)) * 2 + ((d >> 3) & 1);
    Ph[off] = hi; Pl[off] = lo;
}

// ---------------------------------------------------------------------------
// GEMM mainloop. THREE=true: fp16x3. THREE=false: fp16x2 (A-lo dropped).
// ---------------------------------------------------------------------------
template<bool THREE>
__global__ void __launch_bounds__(256, 2) gemm_t_kernel(
    const unsigned* __restrict__ Ah, const unsigned* __restrict__ Al,
    const unsigned* __restrict__ Bh, const unsigned* __restrict__ Bl,
    float* __restrict__ C, int N, int K)
{
    __shared__ unsigned sm[2][4][2048];

    const int tid = threadIdx.x, lane = tid & 31, warp = tid >> 5;
    const int wm = warp >> 2, wn = warp & 3;
    const int m0t = blockIdx.y * 8, n0t = blockIdx.x * 16;
    const int KT = K >> 4;

    const int f0 = tid, f1 = tid + 256;
    const int aM0 = f0 >> 6, aK0 = (f0 & 63) >> 5, aW0 = f0 & 31;
    const int aM1 = f1 >> 6, aK1 = (f1 & 63) >> 5, aW1 = f1 & 31;
    const size_t aS0 = ((size_t)(m0t + aM0) * KT + aK0) * 128 + aW0 * 4;
    const size_t aS1 = ((size_t)(m0t + aM1) * KT + aK1) * 128 + aW1 * 4;
    const int aD0 = (aM0 * 2 + aK0) * 128 + aW0 * 4;
    const int aD1 = (aM1 * 2 + aK1) * 128 + aW1 * 4;
    const int bN0 = f0 >> 5, bK0 = (f0 & 31) >> 4, bW0 = f0 & 15;
    const int bN1 = f1 >> 5, bK1 = (f1 & 31) >> 4, bW1 = f1 & 15;
    const size_t bS0 = ((size_t)(n0t + bN0) * KT + bK0) * 64 + bW0 * 4;
    const size_t bS1 = ((size_t)(n0t + bN1) * KT + bK1) * 64 + bW1 * 4;
    const int bD0 = (bN0 * 2 + bK0) * 64 + bW0 * 4;
    const int bD1 = (bN1 * 2 + bK1) * 64 + bW1 * 4;

    const uint32_t sb = (uint32_t)__cvta_generic_to_shared(&sm[0][0][0]);
    auto issue = [&](int c, int st) {
        const size_t ao = (size_t)c * 256, bo = (size_t)c * 128;
        const uint32_t s0 = sb + (uint32_t)(st * 4) * 8192;
        cpa16(s0 + aD0 * 4,          Ah + aS0 + ao);
        cpa16(s0 + aD1 * 4,          Ah + aS1 + ao);
        if (THREE) {
            cpa16(s0 + 8192  + aD0 * 4,  Al + aS0 + ao);
            cpa16(s0 + 8192  + aD1 * 4,  Al + aS1 + ao);
        }
        cpa16(s0 + 16384 + bD0 * 4,  Bh + bS0 + bo);
        cpa16(s0 + 16384 + bD1 * 4,  Bh + bS1 + bo);
        cpa16(s0 + 24576 + bD0 * 4,  Bl + bS0 + bo);
        cpa16(s0 + 24576 + bD1 * 4,  Bl + bS1 + bo);
        asm volatile("cp.async.commit_group;" ::: "memory");
    };

    float acc[4][4][4];
    #pragma unroll
    for (int i = 0; i < 4; i++)
        #pragma unroll
        for (int j = 0; j < 4; j++)
            #pragma unroll
            for (int r = 0; r < 4; r++) acc[i][j][r] = 0.f;

    const int nc = K >> 5;
    issue(0, 0);

    for (int c = 0; c < nc; c++) {
        const int s = c & 1;
        if (c + 1 < nc) {
            issue(c + 1, s ^ 1);
            asm volatile("cp.async.wait_group 1;" ::: "memory");
        } else {
            asm volatile("cp.async.wait_group 0;" ::: "memory");
        }
        __syncthreads();

        #pragma unroll
        for (int kt = 0; kt < 2; kt++) {
            uint4 a_h[4], a_l[4];
            #pragma unroll
            for (int i = 0; i < 4; i++) {
                int off = ((wm * 4 + i) * 2 + kt) * 128 + lane * 4;
                a_h[i] = *(const uint4*)&sm[s][0][off];
                if (THREE) a_l[i] = *(const uint4*)&sm[s][1][off];
            }
            #pragma unroll
            for (int jp = 0; jp < 2; jp++) {
                uint2 b_h[2], b_l[2];
                #pragma unroll
                for (int jj = 0; jj < 2; jj++) {
                    int off = ((wn * 4 + jp * 2 + jj) * 2 + kt) * 64 + lane * 2;
                    b_h[jj] = *(const uint2*)&sm[s][2][off];
                    b_l[jj] = *(const uint2*)&sm[s][3][off];
                }
                #pragma unroll
                for (int jj = 0; jj < 2; jj++)
                    #pragma unroll
                    for (int i = 0; i < 4; i++)
                        mma16(acc[i][jp*2+jj], a_h[i], b_h[jj]);
                #pragma unroll
                for (int jj = 0; jj < 2; jj++)
                    #pragma unroll
                    for (int i = 0; i < 4; i++)
                        mma16(acc[i][jp*2+jj], a_h[i], b_l[jj]);
                if (THREE) {
                    #pragma unroll
                    for (int jj = 0; jj < 2; jj++)
                        #pragma unroll
                        for (int i = 0; i < 4; i++)
                            mma16(acc[i][jp*2+jj], a_l[i], b_h[jj]);
                }
            }
        }
        __syncthreads();
    }

    const int g = lane >> 2, q = lane & 3;
    const int m0 = blockIdx.y * 128, n0 = blockIdx.x * 128;
    #pragma unroll
    for (int i = 0; i < 4; i++) {
        const int row = m0 + wm * 64 + i * 16 + g;
        #pragma unroll
        for (int j = 0; j < 4; j++) {
            const int colb = n0 + wn * 32 + j * 8;
            if (colb < N) {
                const int col = colb + 2 * q;
                *(float2*)&C[(size_t)row * N + col] =
                    make_float2(acc[i][j][0], acc[i][j][1]);
                *(float2*)&C[(size_t)(row + 8) * N + col] =
                    make_float2(acc[i][j][2], acc[i][j][3]);
            }
        }
    }
}

// ---------------------------------------------------------------------------
__global__ void __launch_bounds__(256) rmsnormA_kernel(
    const float* __restrict__ x, const float* __restrict__ w,
    unsigned* __restrict__ Ph, unsigned* __restrict__ Pl, int ld, int n)
{
    const int row = blockIdx.x;
    const float* xr = x + (size_t)row * ld;
    float s = 0.f;
    for (int i = threadIdx.x; i < n; i += 256) { float v = xr[i]; s += v * v; }
    __shared__ float red[8];
    #pragma unroll
    for (int o = 16; o; o >>= 1) s += __shfl_xor_sync(0xffffffffu, s, o);
    if ((threadIdx.x & 31) == 0) red[threadIdx.x >> 5] = s;
    __syncthreads();
    if (threadIdx.x < 32) {
        float v = (threadIdx.x < 8) ? red[threadIdx.x] : 0.f;
        #pragma unroll
        for (int o = 4; o; o >>= 1) v += __shfl_xor_sync(0xffffffffu, v, o);
        if (threadIdx.x == 0) red[0] = v;
    }
    __syncthreads();
    const float r = rsqrtf(red[0] / (float)n + EPS);
    for (int dp = threadIdx.x; dp < (n >> 1); dp += 256) {
        int d = dp * 2;
        float v0 = w[d] * xr[d] * r, v1 = w[d + 1] * xr[d + 1] * r;
        unsigned hi, lo; split2(v0, v1, hi, lo);
        size_t off = ((size_t)(row >> 4) * (n >> 4) + (d >> 4)) * 128
                   + ((row & 7) * 4 + ((d & 7) >> 1)) * 4
                   + ((d >> 3) & 1) * 2 + ((row >> 3) & 1);
        Ph[off] = hi; Pl[off] = lo;
    }
}

// ---------------------------------------------------------------------------
__global__ void __launch_bounds__(256) assemble_kernel(
    const void* __restrict__ pos_ids)
{
    const int b = blockIdx.x, t0 = 2 * b, tid = threadIdx.x;
    const int h = blockIdx.y;
    __shared__ float cs[2][DR], sn[2][DR], kr[2][DR];
    __shared__ float posv[2];

    if (tid < 2) {
        const int* p32 = (const int*)pos_ids;
        int t = t0 + tid;
        long long pv = (p32[1] == 0) ? ((const long long*)pos_ids)[t]
                                     : (long long)p32[t];
        posv[tid] = (float)pv;
    }
    __syncthreads();
    if (tid < 128) {
        int tok = tid >> 6, i = tid & 63, j = i & 31;
        double e = -((double)(2 * j) / 64.0) * 13.287712379549449;
        float ang = posv[tok] * (float)exp2(e);
        cs[tok][i] = cosf(ang); sn[tok][i] = sinf(ang);
    }
    __syncthreads();
    if (tid < 128) {
        int tok = tid >> 6, i = tid & 63;
        const float* kx = g_kva + (size_t)(t0 + tok) * (KVR + DR) + KVR;
        kr[tok][i] = (i < 32) ? kx[i] * cs[tok][i] - kx[i + 32] * sn[tok][i]
                              : kx[i] * cs[tok][i] + kx[i - 32] * sn[tok][i];
    }
    __syncthreads();

    const float scale = rsqrtf((float)DQK);

    if (tid < 192) {                                  // Q (hi plane only)
        int tok = tid / 96, pp = tid % 96, d = 2 * pp;
        int t = t0 + tok;
        const float* qrow = g_q + (size_t)t * (NH * DQK) + h * DQK;
        float v0, v1;
        if (d < DN) { v0 = qrow[d]; v1 = qrow[d + 1]; }
        else {
            int i = d - DN;
            if (i < 32) {
                v0 = qrow[d]   * cs[tok][i]   - qrow[d + 32] * sn[tok][i];
                v1 = qrow[d+1] * cs[tok][i+1] - qrow[d + 33] * sn[tok][i+1];
            } else {
                v0 = qrow[d]   * cs[tok][i]   + qrow[d - 32] * sn[tok][i];
                v1 = qrow[d+1] * cs[tok][i+1] + qrow[d - 31] * sn[tok][i+1];
            }
        }
        v0 *= scale; v1 *= scale;
        int mt = t >> 4, r = t & 15;
        size_t off = ((size_t)(h * 128 + mt) * 12 + (d >> 4)) * 128
                   + ((r & 7) * 4 + ((d & 7) >> 1)) * 4
                   + (((d >> 3) & 1) * 2 + (r >> 3));
        g_Qh[off] = pack2h(v0, v1);
    }
    if (tid < 192) {                                  // K
        int tok = tid / 96, pp = tid % 96, d = 2 * pp;
        int t = t0 + tok;
        const float* kvrow = g_kvb + (size_t)t * (NH*(DN+DV)) + h * (DN+DV);
        float v0, v1;
        if (d < DN) { v0 = kvrow[d]; v1 = kvrow[d + 1]; }
        else        { v0 = kr[tok][d - DN]; v1 = kr[tok][d - DN + 1]; }
        unsigned hi, lo; split2(v0, v1, hi, lo);
        int nt = t >> 3, n = t & 7;
        size_t off = ((size_t)(h * 256 + nt) * 12 + (d >> 4)) * 64
                   + (n * 4 + ((d & 7) >> 1)) * 2 + ((d >> 3) & 1);
        g_Kh[off] = hi; g_Kl[off] = lo;
    }
    if (tid >= 64 && tid < 192) {                     // V
        int d = tid - 64;
        float v0 = g_kvb[(size_t)t0     * (NH*(DN+DV)) + h*(DN+DV) + DN + d];
        float v1 = g_kvb[(size_t)(t0+1) * (NH*(DN+DV)) + h*(DN+DV) + DN + d];
        unsigned hi, lo; split2(v0, v1, hi, lo);
        size_t off = ((size_t)(h * 128 + (t0 >> 4)) * 16 + (d >> 3)) * 64
                   + ((d & 7) * 4 + ((t0 & 7) >> 1)) * 2 + ((t0 >> 3) & 1);
        g_Vh[off] = hi; g_Vl[off] = lo;
    }
}

// ---------------------------------------------------------------------------
// Flash attention: fp16x2 everywhere (q-lo and P-lo dropped).
// Smem = 2 K/V stages only (QL eliminated).
// ---------------------------------------------------------------------------
constexpr int FL_STAGE = 20480;
constexpr size_t FLASH_SMEM_BYTES = (2 * FL_STAGE) * 4;   // 163840

__global__ void __launch_bounds__(256) flash_kernel()
{
    const int bx = blockIdx.x;
    const int qt = 15 - (bx >> 4);
    const int h  = bx & 15;
    const int q0 = qt * 128;
    const int tid = threadIdx.x, wid = tid >> 5, lane = tid & 31;
    const int g = lane >> 2, q = lane & 3;

    extern __shared__ unsigned smu[];
    const uint32_t sb = (uint32_t)__cvta_generic_to_shared(smu);

    uint4 qh[12];
    {
        const size_t qbase = (size_t)(h * 128 + qt * 8 + wid) * 12 * 128;
        #pragma unroll
        for (int kt = 0; kt < 12; kt++)
            qh[kt] = *(const uint4*)&g_Qh[qbase + kt * 128 + lane * 4];
    }

    const int niter = 2 * (qt + 1);
    const int wrow0 = q0 + wid * 16;

    auto issue = [&](int it, int st) {
        const uint4* gkh = (const uint4*)(g_Kh + (size_t)(h * 256 + it * 8) * 768);
        const uint4* gkl = (const uint4*)(g_Kl + (size_t)(h * 256 + it * 8) * 768);
        const uint4* gvh = (const uint4*)(g_Vh + (size_t)(h * 128 + it * 4) * 1024);
        const uint4* gvl = (const uint4*)(g_Vl + (size_t)(h * 128 + it * 4) * 1024);
        const uint32_t s0 = sb + (uint32_t)st * FL_STAGE * 4;
        #pragma unroll
        for (int j = 0; j < 6; j++) {
            cpa16(s0 +         (j * 256 + tid) * 16, gkh + j * 256 + tid);
            cpa16(s0 + 24576 + (j * 256 + tid) * 16, gkl + j * 256 + tid);
        }
        #pragma unroll
        for (int j = 0; j < 4; j++) {
            cpa16(s0 + 49152 + (j * 256 + tid) * 16, gvh + j * 256 + tid);
            cpa16(s0 + 65536 + (j * 256 + tid) * 16, gvl + j * 256 + tid);
        }
        asm volatile("cp.async.commit_group;" ::: "memory");
    };

    float O[16][4];
    #pragma unroll
    for (int nt = 0; nt < 16; nt++)
        #pragma unroll
        for (int r = 0; r < 4; r++) O[nt][r] = 0.f;
    float m0 = -1e30f, m1 = -1e30f, l0 = 0.f, l1 = 0.f;

    issue(0, 0);

    for (int it = 0; it < niter; it++) {
        const int s = it & 1;
        const int k0 = it * 64;
        if (it + 1 < niter) {
            issue(it + 1, s ^ 1);
            asm volatile("cp.async.wait_group 1;" ::: "memory");
        } else {
            asm volatile("cp.async.wait_group 0;" ::: "memory");
        }
        __syncthreads();

        unsigned* KHs = smu + s * FL_STAGE;
        unsigned* KLs = KHs + 6144;
        unsigned* VHs = KHs + 12288;
        unsigned* VLs = KHs + 16384;

        if (k0 <= wrow0 + 15) {
            float S[8][4];
            #pragma unroll
            for (int nt = 0; nt < 8; nt++)
                #pragma unroll
                for (int r = 0; r < 4; r++) S[nt][r] = 0.f;

            #pragma unroll
            for (int kt = 0; kt < 12; kt++) {
                uint4 qhv = qh[kt];
                #pragma unroll
                for (int nt = 0; nt < 8; nt++) {
                    uint2 kh = *(const uint2*)&KHs[(nt * 12 + kt) * 64 + lane * 2];
                    uint2 kl = *(const uint2*)&KLs[(nt * 12 + kt) * 64 + lane * 2];
                    mma16(S[nt], qhv, kh);
                    mma16(S[nt], qhv, kl);
                }
            }

            if (k0 + 63 > wrow0) {
                const int row0 = wrow0 + g, row1 = row0 + 8;
                #pragma unroll
                for (int nt = 0; nt < 8; nt++) {
                    int col = k0 + nt * 8 + 2 * q;
                    if (col     > row0) S[nt][0] = -1e30f;
                    if (col + 1 > row0) S[nt][1] = -1e30f;
                    if (col     > row1) S[nt][2] = -1e30f;
                    if (col + 1 > row1) S[nt][3] = -1e30f;
                }
            }

            float rm0 = -1e30f, rm1 = -1e30f;
            #pragma unroll
            for (int nt = 0; nt < 8; nt++) {
                rm0 = fmaxf(rm0, fmaxf(S[nt][0], S[nt][1]));
                rm1 = fmaxf(rm1, fmaxf(S[nt][2], S[nt][3]));
            }
            rm0 = fmaxf(rm0, __shfl_xor_sync(0xffffffffu, rm0, 1));
            rm0 = fmaxf(rm0, __shfl_xor_sync(0xffffffffu, rm0, 2));
            rm1 = fmaxf(rm1, __shfl_xor_sync(0xffffffffu, rm1, 1));
            rm1 = fmaxf(rm1, __shfl_xor_sync(0xffffffffu, rm1, 2));

            float mn0 = fmaxf(m0, rm0), mn1 = fmaxf(m1, rm1);
            float a0 = __expf(m0 - mn0), a1 = __expf(m1 - mn1);

            unsigned PH[8], P8H[8];
            float s0 = 0.f, s1 = 0.f;
            #pragma unroll
            for (int nt = 0; nt < 8; nt++) {
                float p00 = __expf(S[nt][0] - mn0);
                float p01 = __expf(S[nt][1] - mn0);
                float p10 = __expf(S[nt][2] - mn1);
                float p11 = __expf(S[nt][3] - mn1);
                s0 += p00 + p01; s1 += p10 + p11;
                PH[nt]  = pack2h(p00, p01);
                P8H[nt] = pack2h(p10, p11);
            }
            s0 += __shfl_xor_sync(0xffffffffu, s0, 1);
            s0 += __shfl_xor_sync(0xffffffffu, s0, 2);
            s1 += __shfl_xor_sync(0xffffffffu, s1, 1);
            s1 += __shfl_xor_sync(0xffffffffu, s1, 2);

            l0 = l0 * a0 + s0; l1 = l1 * a1 + s1;
            m0 = mn0; m1 = mn1;

            #pragma unroll
            for (int nt = 0; nt < 16; nt++) {
                O[nt][0] *= a0; O[nt][1] *= a0;
                O[nt][2] *= a1; O[nt][3] *= a1;
            }

            #pragma unroll
            for (int kt2 = 0; kt2 < 4; kt2++) {
                uint4 ah = make_uint4(PH[2*kt2], P8H[2*kt2],
                                      PH[2*kt2+1], P8H[2*kt2+1]);
                #pragma unroll
                for (int nt = 0; nt < 16; nt++) {
                    uint2 vh = *(const uint2*)&VHs[(kt2 * 16 + nt) * 64 + lane * 2];
                    uint2 vl = *(const uint2*)&VLs[(kt2 * 16 + nt) * 64 + lane * 2];
                    mma16(O[nt], ah, vh);
                    mma16(O[nt], ah, vl);
                }
            }
        }
        __syncthreads();
    }

    const float inv0 = __fdividef(1.f, l0), inv1 = __fdividef(1.f, l1);
    const int row0 = wrow0 + g;
    const size_t baseRow = (size_t)(row0 >> 4) * 128;
    #pragma unroll
    for (int nt = 0; nt < 16; nt++) {
        const int ktv = h * 8 + (nt >> 1);
        const size_t off = (baseRow + ktv) * 128 + lane * 4 + (nt & 1) * 2;
        unsigned hi, lo;
        split2(O[nt][0] * inv0, O[nt][1] * inv0, hi, lo);
        g_AatH[off] = hi; g_AatL[off] = lo;
        split2(O[nt][2] * inv1, O[nt][3] * inv1, hi, lo);
        g_AatH[off + 1] = hi; g_AatL[off + 1] = lo;
    }
}

// ---------------------------------------------------------------------------
extern "C" void kernel_launch(void* const* d_in, const int* in_sizes, int n_in,
                              void* d_out, int out_size)
{
    const float* hs       = (const float*)d_in[0];
    const void*  pos_ids  = d_in[1];
    const float* q_a_w    = (const float*)d_in[2];
    const float* q_a_ln_w = (const float*)d_in[3];
    const float* q_b_w    = (const float*)d_in[4];
    const float* kv_a_w   = (const float*)d_in[5];
    const float* kv_a_ln_w= (const float*)d_in[6];
    const float* kv_b_w   = (const float*)d_in[7];
    const float* o_w      = (const float*)d_in[8];
    float*       out      = (float*)d_out;

    float *p_qa, *p_q, *p_kva, *p_kvb;
    cudaGetSymbolAddress((void**)&p_qa,  g_qa);
    cudaGetSymbolAddress((void**)&p_q,   g_q);
    cudaGetSymbolAddress((void**)&p_kva, g_kva);
    cudaGetSymbolAddress((void**)&p_kvb, g_kvb);
    unsigned *AhsH,*AhsL,*AqaH,*AqaL,*AkvH,*AkvL,*AatH,*AatL;
    unsigned *BqaH,*BqaL,*BqbH,*BqbL,*BkaH,*BkaL,*BkbH,*BkbL,*BowH,*BowL;
    cudaGetSymbolAddress((void**)&AhsH, g_AhsH); cudaGetSymbolAddress((void**)&AhsL, g_AhsL);
    cudaGetSymbolAddress((void**)&AqaH, g_AqaH); cudaGetSymbolAddress((void**)&AqaL, g_AqaL);
    cudaGetSymbolAddress((void**)&AkvH, g_AkvH); cudaGetSymbolAddress((void**)&AkvL, g_AkvL);
    cudaGetSymbolAddress((void**)&AatH, g_AatH); cudaGetSymbolAddress((void**)&AatL, g_AatL);
    cudaGetSymbolAddress((void**)&BqaH, g_BqaH); cudaGetSymbolAddress((void**)&BqaL, g_BqaL);
    cudaGetSymbolAddress((void**)&BqbH, g_BqbH); cudaGetSymbolAddress((void**)&BqbL, g_BqbL);
    cudaGetSymbolAddress((void**)&BkaH, g_BkaH); cudaGetSymbolAddress((void**)&BkaL, g_BkaL);
    cudaGetSymbolAddress((void**)&BkbH, g_BkbH); cudaGetSymbolAddress((void**)&BkbL, g_BkbL);
    cudaGetSymbolAddress((void**)&BowH, g_BowH); cudaGetSymbolAddress((void**)&BowL, g_BowL);

    cudaFuncSetAttribute(flash_kernel,
                         cudaFuncAttributeMaxDynamicSharedMemorySize,
                         (int)FLASH_SMEM_BYTES);

    static cudaStream_t sA = nullptr, sB = nullptr;
    static cudaEvent_t evRoot, evA, evW1, evW2, evKV;
    if (!sA) {
        cudaStreamCreateWithFlags(&sA, cudaStreamNonBlocking);
        cudaStreamCreateWithFlags(&sB, cudaStreamNonBlocking);
        cudaEventCreateWithFlags(&evRoot, cudaEventDisableTiming);
        cudaEventCreateWithFlags(&evA, cudaEventDisableTiming);
        cudaEventCreateWithFlags(&evW1, cudaEventDisableTiming);
        cudaEventCreateWithFlags(&evW2, cudaEventDisableTiming);
        cudaEventCreateWithFlags(&evKV, cudaEventDisableTiming);
    }

    // fork
    cudaEventRecord(evRoot, 0);
    cudaStreamWaitEvent(sA, evRoot, 0);
    cudaStreamWaitEvent(sB, evRoot, 0);

    // main stream: q chain
    convB_kernel<<<6144, 256>>>(q_a_w, BqaH, BqaL, QR, HID);
    convA_kernel<<<8192, 256>>>(hs, AhsH, AhsL, HID);
    cudaEventRecord(evA, 0);
    gemm_t_kernel<true><<<dim3(12, 16), 256>>>(AhsH, AhsL, BqaH, BqaL, p_qa, QR, HID);
    rmsnormA_kernel<<<S_LEN, 256>>>(p_qa, q_a_ln_w, AqaH, AqaL, QR, QR);

    // sA: kv chain
    convB_kernel<<<2560, 256, 0, sA>>>(kv_a_w, BkaH, BkaL, KVR + DR, HID);
    convB_kernel<<<4096, 256, 0, sA>>>(kv_b_w, BkbH, BkbL, NH * (DN + DV), KVR);
    cudaStreamWaitEvent(sA, evA, 0);
    gemm_t_kernel<true><<<dim3(5, 16), 256, 0, sA>>>(AhsH, AhsL, BkaH, BkaL, p_kva,
                                                     KVR + DR, HID);
    rmsnormA_kernel<<<S_LEN, 256, 0, sA>>>(p_kva, kv_a_ln_w, AkvH, AkvL,
                                           KVR + DR, KVR);
    gemm_t_kernel<true><<<dim3(32, 16), 256, 0, sA>>>(AkvH, AkvL, BkbH, BkbL, p_kvb,
                                                      NH * (DN + DV), KVR);
    cudaEventRecord(evKV, sA);

    // sB: remaining weight conversions
    convB_kernel<<<9216, 256, 0, sB>>>(q_b_w, BqbH, BqbL, NH * DQK, QR);
    cudaEventRecord(evW1, sB);
    convB_kernel<<<8192, 256, 0, sB>>>(o_w, BowH, BowL, HID, HID);
    cudaEventRecord(evW2, sB);

    // join and finish on main stream
    cudaStreamWaitEvent(0, evW1, 0);
    gemm_t_kernel<true><<<dim3(24, 16), 256>>>(AqaH, AqaL, BqbH, BqbL, p_q,
                                               NH * DQK, QR);
    cudaStreamWaitEvent(0, evKV, 0);
    assemble_kernel<<<dim3(S_LEN / 2, NH), 256>>>(pos_ids);
    flash_kernel<<<256, 256, FLASH_SMEM_BYTES>>>();
    cudaStreamWaitEvent(0, evW2, 0);
    gemm_t_kernel<false><<<dim3(16, 16), 256>>>(AatH, AatL, BowH, BowL, out,
                                                HID, HID);
}